// round 1
// baseline (speedup 1.0000x reference)
#include <cuda_runtime.h>
#include <math.h>

#define Bn 2
#define Sn 2048
#define Dn 2048
#define Hn 16
#define HDn 128
#define Tn (Bn*Sn)      // 4096 tokens
#define En 8
#define KKn 2
#define Fn 4096

// ---------------- scratch (device globals; no runtime allocation) ----------------
__device__ float g_h1[Tn*Dn];
__device__ float g_q[Tn*Dn];
__device__ float g_k[Tn*Dn];
__device__ float g_v[Tn*Dn];
__device__ float g_ctx[Tn*Dn];
__device__ float g_x1[Tn*Dn];
__device__ float g_h2[Tn*Dn];
__device__ float g_act[(size_t)Tn*KKn*Fn];   // compact (token,expert) activation rows
__device__ int   g_cnt[En];
__device__ int   g_off[En];
__device__ int   g_run[En];
__device__ int   g_tok_e[Tn*KKn];
__device__ float g_tok_w[Tn*KKn];
__device__ int   g_list_tok[Tn*KKn];
__device__ float g_list_w[Tn*KKn];

// ---------------- RMSNorm ----------------
__global__ void k_rmsnorm(const float* __restrict__ x, const float* __restrict__ w,
                          float* __restrict__ out) {
    int row = blockIdx.x;
    const float* xr = x + (size_t)row * Dn;
    float ss = 0.f;
    for (int i = threadIdx.x; i < Dn; i += 256) { float v = xr[i]; ss += v * v; }
    __shared__ float sh[256];
    sh[threadIdx.x] = ss;
    __syncthreads();
    for (int o = 128; o > 0; o >>= 1) {
        if (threadIdx.x < o) sh[threadIdx.x] += sh[threadIdx.x + o];
        __syncthreads();
    }
    float inv = rsqrtf(sh[0] / (float)Dn + 1e-6f);
    float* orow = out + (size_t)row * Dn;
    for (int i = threadIdx.x; i < Dn; i += 256) orow[i] = xr[i] * inv * w[i];
}

// ---------------- generic C = A(MxK) @ B(NxK)^T (+ optional residual R) ----------------
__global__ __launch_bounds__(256) void k_gemm(const float* __restrict__ A,
                                              const float* __restrict__ B,
                                              const float* __restrict__ R,
                                              float* __restrict__ C,
                                              int M, int N, int Kd) {
    __shared__ float As[16][64];
    __shared__ float Bs[16][64];
    int tid = threadIdx.x;
    int tx = tid & 15, ty = tid >> 4;
    int m0 = blockIdx.y * 64, n0 = blockIdx.x * 64;
    int lrow = tid >> 2;
    int lk = (tid & 3) * 4;
    float acc[4][4] = {};
    for (int k0 = 0; k0 < Kd; k0 += 16) {
        float4 av = *(const float4*)(A + (size_t)(m0 + lrow) * Kd + k0 + lk);
        float4 bv = (n0 + lrow < N)
                        ? *(const float4*)(B + (size_t)(n0 + lrow) * Kd + k0 + lk)
                        : make_float4(0.f, 0.f, 0.f, 0.f);
        As[lk + 0][lrow] = av.x; As[lk + 1][lrow] = av.y;
        As[lk + 2][lrow] = av.z; As[lk + 3][lrow] = av.w;
        Bs[lk + 0][lrow] = bv.x; Bs[lk + 1][lrow] = bv.y;
        Bs[lk + 2][lrow] = bv.z; Bs[lk + 3][lrow] = bv.w;
        __syncthreads();
#pragma unroll
        for (int kk = 0; kk < 16; kk++) {
            float a0 = As[kk][ty * 4 + 0], a1 = As[kk][ty * 4 + 1];
            float a2 = As[kk][ty * 4 + 2], a3 = As[kk][ty * 4 + 3];
            float b0 = Bs[kk][tx], b1 = Bs[kk][tx + 16];
            float b2 = Bs[kk][tx + 32], b3 = Bs[kk][tx + 48];
            acc[0][0] += a0 * b0; acc[0][1] += a0 * b1; acc[0][2] += a0 * b2; acc[0][3] += a0 * b3;
            acc[1][0] += a1 * b0; acc[1][1] += a1 * b1; acc[1][2] += a1 * b2; acc[1][3] += a1 * b3;
            acc[2][0] += a2 * b0; acc[2][1] += a2 * b1; acc[2][2] += a2 * b2; acc[2][3] += a2 * b3;
            acc[3][0] += a3 * b0; acc[3][1] += a3 * b1; acc[3][2] += a3 * b2; acc[3][3] += a3 * b3;
        }
        __syncthreads();
    }
#pragma unroll
    for (int i = 0; i < 4; i++)
#pragma unroll
        for (int j = 0; j < 4; j++) {
            int r = m0 + ty * 4 + i;
            int c = n0 + tx + 16 * j;
            if (r < M && c < N) {
                float v = acc[i][j];
                if (R) v += R[(size_t)r * N + c];
                C[(size_t)r * N + c] = v;
            }
        }
}

// ---------------- RoPE (in place on q,k; layout (T, H*HD)) ----------------
__global__ void k_rope(float* __restrict__ q, float* __restrict__ k) {
    int gid = blockIdx.x * 256 + threadIdx.x;
    if (gid >= Tn * Hn * 64) return;
    int i = gid & 63;
    int h = (gid >> 6) & (Hn - 1);
    int t = gid >> 10;           // 6+4 bits
    int s = t & (Sn - 1);
    float inv = powf(10000.0f, -(float)i / 64.0f);
    float ang = (float)s * inv;
    float sn, c;
    sincosf(ang, &sn, &c);
    size_t base = (size_t)t * Dn + h * HDn;
    float q1 = q[base + i], q2 = q[base + i + 64];
    q[base + i]      = q1 * c - q2 * sn;
    q[base + i + 64] = q2 * c + q1 * sn;
    float k1 = k[base + i], k2 = k[base + i + 64];
    k[base + i]      = k1 * c - k2 * sn;
    k[base + i + 64] = k2 * c + k1 * sn;
}

// ---------------- causal attention, flash-style 64x64 tiles, fp32 ----------------
#define ATTN_SMEM_FLOATS (64*128 + 64*129 + 64*64 + 64*3)
__global__ __launch_bounds__(256) void k_attn(const float* __restrict__ q,
                                              const float* __restrict__ k,
                                              const float* __restrict__ v,
                                              float* __restrict__ ctx) {
    extern __shared__ float sm[];
    float* Qs   = sm;                 // 64 x 128
    float* KVs  = Qs + 64 * 128;      // 64 x 129 (padded)
    float* Ss   = KVs + 64 * 129;     // 64 x 64
    float* m_s  = Ss + 4096;
    float* l_s  = m_s + 64;
    float* al_s = l_s + 64;
    int tid = threadIdx.x;
    int qt = blockIdx.x;
    int bh = blockIdx.y;
    int b = bh >> 4, h = bh & 15;
    const float scale = 0.08838834764831845f;   // 1/sqrt(128)

    for (int idx = tid; idx < 64 * 128; idx += 256) {
        int r = idx >> 7, c = idx & 127;
        Qs[idx] = q[(size_t)(b * Sn + qt * 64 + r) * Dn + h * HDn + c];
    }
    if (tid < 64) { m_s[tid] = -1e30f; l_s[tid] = 0.f; }
    float acc[8][4] = {};
    int tx = tid & 31, ty = tid >> 5;

    for (int kt = 0; kt <= qt; kt++) {
        __syncthreads();
        for (int idx = tid; idx < 64 * 128; idx += 256) {
            int r = idx >> 7, c = idx & 127;
            KVs[r * 129 + c] = k[(size_t)(b * Sn + kt * 64 + r) * Dn + h * HDn + c];
        }
        __syncthreads();
        for (int idx = tid; idx < 4096; idx += 256) {
            int r = idx >> 6, j = idx & 63;
            const float* qp = Qs + r * 128;
            const float* kp = KVs + j * 129;
            float s = 0.f;
#pragma unroll 16
            for (int kk = 0; kk < 128; kk++) s += qp[kk] * kp[kk];
            s *= scale;
            if (kt * 64 + j > qt * 64 + r) s = -1e30f;
            Ss[idx] = s;
        }
        __syncthreads();
        if (tid < 64) {
            int r = tid;
            float* sr = Ss + r * 64;
            float mo = m_s[r], tm = -1e30f;
            for (int j = 0; j < 64; j++) tm = fmaxf(tm, sr[j]);
            float nm = fmaxf(mo, tm);
            float a = expf(mo - nm);
            float sum = 0.f;
            for (int j = 0; j < 64; j++) { float p = expf(sr[j] - nm); sr[j] = p; sum += p; }
            l_s[r] = l_s[r] * a + sum;
            m_s[r] = nm;
            al_s[r] = a;
        }
        __syncthreads();
        for (int idx = tid; idx < 64 * 128; idx += 256) {
            int r = idx >> 7, c = idx & 127;
            KVs[r * 129 + c] = v[(size_t)(b * Sn + kt * 64 + r) * Dn + h * HDn + c];
        }
        __syncthreads();
#pragma unroll
        for (int i = 0; i < 8; i++) {
            int r = ty * 8 + i;
            float a = al_s[r];
            const float* pr = Ss + r * 64;
            float c0 = acc[i][0] * a, c1 = acc[i][1] * a;
            float c2 = acc[i][2] * a, c3 = acc[i][3] * a;
            for (int j = 0; j < 64; j++) {
                float p = pr[j];
                const float* vp = KVs + j * 129 + tx;
                c0 += p * vp[0];
                c1 += p * vp[32];
                c2 += p * vp[64];
                c3 += p * vp[96];
            }
            acc[i][0] = c0; acc[i][1] = c1; acc[i][2] = c2; acc[i][3] = c3;
        }
    }
#pragma unroll
    for (int i = 0; i < 8; i++) {
        int r = ty * 8 + i;
        float invl = 1.f / l_s[r];
        size_t base = (size_t)(b * Sn + qt * 64 + r) * Dn + h * HDn + tx;
        ctx[base]      = acc[i][0] * invl;
        ctx[base + 32] = acc[i][1] * invl;
        ctx[base + 64] = acc[i][2] * invl;
        ctx[base + 96] = acc[i][3] * invl;
    }
}

// ---------------- MoE routing ----------------
__global__ void k_zero() { if (threadIdx.x < En) g_cnt[threadIdx.x] = 0; }

__global__ void k_route(const float* __restrict__ h2, const float* __restrict__ gw) {
    int t = blockIdx.x;
    int lane = threadIdx.x & 31, wid = threadIdx.x >> 5;   // 8 warps = 8 experts
    const float* hr = h2 + (size_t)t * Dn;
    const float* gr = gw + (size_t)wid * Dn;
    float s = 0.f;
    for (int i = lane; i < Dn; i += 32) s += hr[i] * gr[i];
    for (int o = 16; o; o >>= 1) s += __shfl_down_sync(0xffffffffu, s, o);
    __shared__ float lg[En];
    if (lane == 0) lg[wid] = s;
    __syncthreads();
    if (threadIdx.x == 0) {
        float mx = lg[0];
        for (int e = 1; e < En; e++) mx = fmaxf(mx, lg[e]);
        float p[En];
        for (int e = 0; e < En; e++) p[e] = expf(lg[e] - mx);
        int i1 = 0;
        for (int e = 1; e < En; e++) if (p[e] > p[i1]) i1 = e;
        int i2 = (i1 == 0) ? 1 : 0;
        for (int e = 0; e < En; e++) { if (e == i1) continue; if (p[e] > p[i2]) i2 = e; }
        float norm = p[i1] + p[i2];
        g_tok_e[t * 2]     = i1; g_tok_w[t * 2]     = p[i1] / norm;
        g_tok_e[t * 2 + 1] = i2; g_tok_w[t * 2 + 1] = p[i2] / norm;
        atomicAdd(&g_cnt[i1], 1);
        atomicAdd(&g_cnt[i2], 1);
    }
}

__global__ void k_scan() {
    if (threadIdx.x == 0) {
        int o = 0;
        for (int e = 0; e < En; e++) { g_off[e] = o; o += g_cnt[e]; g_run[e] = 0; }
    }
}

__global__ void k_place() {
    int t = blockIdx.x * 256 + threadIdx.x;
    if (t >= Tn) return;
    for (int kk = 0; kk < KKn; kk++) {
        int e = g_tok_e[t * 2 + kk];
        int pos = g_off[e] + atomicAdd(&g_run[e], 1);
        g_list_tok[pos] = t;
        g_list_w[pos] = g_tok_w[t * 2 + kk];
    }
}

// ---------------- MoE GEMM1: act = silu(h@w1^T) * (h@w3^T), gathered rows ----------------
__global__ __launch_bounds__(256) void k_moe1(const float* __restrict__ h2,
                                              const float* __restrict__ w1,
                                              const float* __restrict__ w3) {
    int e = blockIdx.z;
    int cnt = g_cnt[e];
    int m0 = blockIdx.y * 64;
    if (m0 >= cnt) return;
    int off = g_off[e];
    int n0 = blockIdx.x * 64;
    __shared__ float As[16][64], B1s[16][64], B2s[16][64];
    __shared__ int toks[64];
    int tid = threadIdx.x;
    if (tid < 64) toks[tid] = (m0 + tid < cnt) ? g_list_tok[off + m0 + tid] : g_list_tok[off];
    __syncthreads();
    int tx = tid & 15, ty = tid >> 4;
    int lrow = tid >> 2, lk = (tid & 3) * 4;
    const float* B1 = w1 + (size_t)e * Fn * Dn;
    const float* B2 = w3 + (size_t)e * Fn * Dn;
    float aU[4][4] = {}, aG[4][4] = {};
    for (int k0 = 0; k0 < Dn; k0 += 16) {
        float4 av  = *(const float4*)(h2 + (size_t)toks[lrow] * Dn + k0 + lk);
        float4 b1v = *(const float4*)(B1 + (size_t)(n0 + lrow) * Dn + k0 + lk);
        float4 b2v = *(const float4*)(B2 + (size_t)(n0 + lrow) * Dn + k0 + lk);
        As[lk + 0][lrow] = av.x;  As[lk + 1][lrow] = av.y;
        As[lk + 2][lrow] = av.z;  As[lk + 3][lrow] = av.w;
        B1s[lk + 0][lrow] = b1v.x; B1s[lk + 1][lrow] = b1v.y;
        B1s[lk + 2][lrow] = b1v.z; B1s[lk + 3][lrow] = b1v.w;
        B2s[lk + 0][lrow] = b2v.x; B2s[lk + 1][lrow] = b2v.y;
        B2s[lk + 2][lrow] = b2v.z; B2s[lk + 3][lrow] = b2v.w;
        __syncthreads();
#pragma unroll
        for (int kk = 0; kk < 16; kk++) {
            float a0 = As[kk][ty * 4 + 0], a1 = As[kk][ty * 4 + 1];
            float a2 = As[kk][ty * 4 + 2], a3 = As[kk][ty * 4 + 3];
#pragma unroll
            for (int j = 0; j < 4; j++) {
                float u = B1s[kk][tx + 16 * j];
                float g = B2s[kk][tx + 16 * j];
                aU[0][j] += a0 * u; aU[1][j] += a1 * u; aU[2][j] += a2 * u; aU[3][j] += a3 * u;
                aG[0][j] += a0 * g; aG[1][j] += a1 * g; aG[2][j] += a2 * g; aG[3][j] += a3 * g;
            }
        }
        __syncthreads();
    }
#pragma unroll
    for (int i = 0; i < 4; i++)
#pragma unroll
        for (int j = 0; j < 4; j++) {
            int r = m0 + ty * 4 + i;
            if (r < cnt) {
                int c = n0 + tx + 16 * j;
                float u = aU[i][j], g = aG[i][j];
                float si = u / (1.f + expf(-u));
                g_act[(size_t)(off + r) * Fn + c] = si * g;
            }
        }
}

// ---------------- MoE GEMM2: out[t] += w * act @ w2^T (atomic scatter) ----------------
__global__ __launch_bounds__(256) void k_moe2(const float* __restrict__ w2,
                                              float* __restrict__ out) {
    int e = blockIdx.z;
    int cnt = g_cnt[e];
    int m0 = blockIdx.y * 64;
    if (m0 >= cnt) return;
    int off = g_off[e];
    int n0 = blockIdx.x * 64;
    __shared__ float As[16][64], Bs[16][64];
    int tid = threadIdx.x;
    int tx = tid & 15, ty = tid >> 4;
    int lrow = tid >> 2, lk = (tid & 3) * 4;
    const float* B = w2 + (size_t)e * Dn * Fn;
    float acc[4][4] = {};
    int arow = m0 + lrow;
    if (arow >= cnt) arow = m0;   // clamp to valid row (garbage, not stored)
    for (int k0 = 0; k0 < Fn; k0 += 16) {
        float4 av = *(const float4*)(g_act + (size_t)(off + arow) * Fn + k0 + lk);
        float4 bv = *(const float4*)(B + (size_t)(n0 + lrow) * Fn + k0 + lk);
        As[lk + 0][lrow] = av.x; As[lk + 1][lrow] = av.y;
        As[lk + 2][lrow] = av.z; As[lk + 3][lrow] = av.w;
        Bs[lk + 0][lrow] = bv.x; Bs[lk + 1][lrow] = bv.y;
        Bs[lk + 2][lrow] = bv.z; Bs[lk + 3][lrow] = bv.w;
        __syncthreads();
#pragma unroll
        for (int kk = 0; kk < 16; kk++) {
            float a0 = As[kk][ty * 4 + 0], a1 = As[kk][ty * 4 + 1];
            float a2 = As[kk][ty * 4 + 2], a3 = As[kk][ty * 4 + 3];
            float b0 = Bs[kk][tx], b1 = Bs[kk][tx + 16];
            float b2 = Bs[kk][tx + 32], b3 = Bs[kk][tx + 48];
            acc[0][0] += a0 * b0; acc[0][1] += a0 * b1; acc[0][2] += a0 * b2; acc[0][3] += a0 * b3;
            acc[1][0] += a1 * b0; acc[1][1] += a1 * b1; acc[1][2] += a1 * b2; acc[1][3] += a1 * b3;
            acc[2][0] += a2 * b0; acc[2][1] += a2 * b1; acc[2][2] += a2 * b2; acc[2][3] += a2 * b3;
            acc[3][0] += a3 * b0; acc[3][1] += a3 * b1; acc[3][2] += a3 * b2; acc[3][3] += a3 * b3;
        }
        __syncthreads();
    }
#pragma unroll
    for (int i = 0; i < 4; i++) {
        int r = m0 + ty * 4 + i;
        if (r < cnt) {
            int t = g_list_tok[off + r];
            float wgt = g_list_w[off + r];
#pragma unroll
            for (int j = 0; j < 4; j++) {
                int c = n0 + tx + 16 * j;
                atomicAdd(&out[(size_t)t * Dn + c], wgt * acc[i][j]);
            }
        }
    }
}

// ---------------- out = x1 (residual init before MoE scatter) ----------------
__global__ void k_copy(float* __restrict__ out) {
    size_t i = (size_t)blockIdx.x * 256 + threadIdx.x;
    out[i] = g_x1[i];
}

extern "C" void kernel_launch(void* const* d_in, const int* in_sizes, int n_in,
                              void* d_out, int out_size) {
    (void)in_sizes; (void)n_in; (void)out_size;
    const float* x   = (const float*)d_in[0];
    // d_in[1] attention_mask (causal, applied analytically), d_in[2] position_ids (arange)
    const float* ln1 = (const float*)d_in[3];
    const float* wq  = (const float*)d_in[4];
    const float* wk  = (const float*)d_in[5];
    const float* wv  = (const float*)d_in[6];
    const float* wo  = (const float*)d_in[7];
    const float* ln2 = (const float*)d_in[8];
    const float* gw  = (const float*)d_in[9];
    const float* w1  = (const float*)d_in[10];
    const float* w3  = (const float*)d_in[11];
    const float* w2  = (const float*)d_in[12];
    float* out = (float*)d_out;

    float *h1, *qb, *kb, *vb, *cb, *x1b, *h2b;
    cudaGetSymbolAddress((void**)&h1,  g_h1);
    cudaGetSymbolAddress((void**)&qb,  g_q);
    cudaGetSymbolAddress((void**)&kb,  g_k);
    cudaGetSymbolAddress((void**)&vb,  g_v);
    cudaGetSymbolAddress((void**)&cb,  g_ctx);
    cudaGetSymbolAddress((void**)&x1b, g_x1);
    cudaGetSymbolAddress((void**)&h2b, g_h2);

    const int smem_attn = ATTN_SMEM_FLOATS * 4;
    cudaFuncSetAttribute(k_attn, cudaFuncAttributeMaxDynamicSharedMemorySize, smem_attn);

    // 1. RMSNorm 1
    k_rmsnorm<<<Tn, 256>>>(x, ln1, h1);
    // 2. QKV projections
    dim3 g1(Dn / 64, Tn / 64);
    k_gemm<<<g1, 256>>>(h1, wq, nullptr, qb, Tn, Dn, Dn);
    k_gemm<<<g1, 256>>>(h1, wk, nullptr, kb, Tn, Dn, Dn);
    k_gemm<<<g1, 256>>>(h1, wv, nullptr, vb, Tn, Dn, Dn);
    // 3. RoPE
    k_rope<<<(Tn * Hn * 64) / 256, 256>>>(qb, kb);
    // 4. attention
    dim3 ga(Sn / 64, Bn * Hn);
    k_attn<<<ga, 256, smem_attn>>>(qb, kb, vb, cb);
    // 5. O projection + residual
    k_gemm<<<g1, 256>>>(cb, wo, x, x1b, Tn, Dn, Dn);
    // 6. RMSNorm 2
    k_rmsnorm<<<Tn, 256>>>(x1b, ln2, h2b);
    // 7. routing
    k_zero<<<1, 32>>>();
    k_route<<<Tn, 256>>>(h2b, gw);
    k_scan<<<1, 32>>>();
    k_place<<<Tn / 256, 256>>>();
    // 8. MoE expert GEMMs
    dim3 gm1(Fn / 64, Tn / 64, En);
    k_moe1<<<gm1, 256>>>(h2b, w1, w3);
    k_copy<<<(Tn * Dn) / 256, 256>>>(out);
    dim3 gm2(Dn / 64, Tn / 64, En);
    k_moe2<<<gm2, 256>>>(w2, out);
}

// round 2
// speedup vs baseline: 2.2159x; 2.2159x over previous
#include <cuda_runtime.h>
#include <math.h>
#include <stdint.h>

#define Bn 2
#define Sn 2048
#define Dn 2048
#define Hn 16
#define HDn 128
#define Tn (Bn*Sn)      // 4096 tokens
#define En 8
#define KKn 2
#define Fn 4096

// ---------------- scratch (device globals; no runtime allocation) ----------------
__device__ float g_h1[Tn*Dn];
__device__ float g_q[Tn*Dn];
__device__ float g_k[Tn*Dn];
__device__ float g_v[Tn*Dn];
__device__ float g_ctx[Tn*Dn];
__device__ float g_x1[Tn*Dn];
__device__ float g_h2[Tn*Dn];
__device__ float g_act[(size_t)Tn*KKn*Fn];   // compact (token,expert) activation rows
__device__ float g_ffn[(size_t)Tn*KKn*Dn];   // expert FFN outputs (compact rows)
__device__ int   g_cnt[En];
__device__ int   g_off[En];
__device__ int   g_run[En];
__device__ int   g_tok_e[Tn*KKn];
__device__ float g_tok_w[Tn*KKn];
__device__ int   g_tok_pos[Tn*KKn];
__device__ int   g_list_tok[Tn*KKn];

__device__ __forceinline__ uint32_t f2tf(float f) {
    uint32_t u;
    asm("cvt.rna.tf32.f32 %0, %1;" : "=r"(u) : "f"(f));
    return u;
}

__device__ __forceinline__ void mma8(float* d, const uint32_t* a, const uint32_t* b) {
    asm volatile(
        "mma.sync.aligned.m16n8k8.row.col.f32.tf32.tf32.f32 "
        "{%0,%1,%2,%3}, {%4,%5,%6,%7}, {%8,%9}, {%0,%1,%2,%3};"
        : "+f"(d[0]), "+f"(d[1]), "+f"(d[2]), "+f"(d[3])
        : "r"(a[0]), "r"(a[1]), "r"(a[2]), "r"(a[3]), "r"(b[0]), "r"(b[1]));
}

// ---------------- RMSNorm ----------------
__global__ void k_rmsnorm(const float* __restrict__ x, const float* __restrict__ w,
                          float* __restrict__ out) {
    int row = blockIdx.x;
    const float* xr = x + (size_t)row * Dn;
    float ss = 0.f;
    for (int i = threadIdx.x; i < Dn; i += 256) { float v = xr[i]; ss += v * v; }
    __shared__ float sh[256];
    sh[threadIdx.x] = ss;
    __syncthreads();
    for (int o = 128; o > 0; o >>= 1) {
        if (threadIdx.x < o) sh[threadIdx.x] += sh[threadIdx.x + o];
        __syncthreads();
    }
    float inv = rsqrtf(sh[0] / (float)Dn + 1e-6f);
    float* orow = out + (size_t)row * Dn;
    for (int i = threadIdx.x; i < Dn; i += 256) orow[i] = xr[i] * inv * w[i];
}

// =====================================================================
// tf32 tensor-core GEMM: C(MxN) = A(MxK) @ B(NxK)^T (+ optional residual)
// CTA tile 128x128x16, 8 warps of 64x32, double-buffered fragment-major smem
// =====================================================================
__global__ __launch_bounds__(256) void k_mma_gemm(const float* __restrict__ A,
                                                  const float* __restrict__ B,
                                                  const float* __restrict__ R,
                                                  float* __restrict__ C,
                                                  int M, int N, int K) {
    __shared__ uint32_t As[2][8][2][32][4];   // [buf][mfrag][kk8][lane][slot]
    __shared__ uint32_t Bs[2][16][2][32][2];  // [buf][nfrag][kk8][lane][slot]
    int tid = threadIdx.x;
    int m0 = blockIdx.y * 128, n0 = blockIdx.x * 128;
    int lane = tid & 31, w = tid >> 5, wm = w >> 2, wn = w & 3;
    float acc[4][4][4] = {};
    float4 pa0, pa1, pb0, pb1;

#define GLDA(k0, i) (*(const float4*)(A + (size_t)(m0 + ((tid + 256*(i)) >> 2)) * K + (k0) + ((tid + 256*(i)) & 3) * 4))
#define GLDB(k0, i) (*(const float4*)(B + (size_t)(n0 + ((tid + 256*(i)) >> 2)) * K + (k0) + ((tid + 256*(i)) & 3) * 4))
#define STA(buf, i, v) { int idx_ = tid + 256*(i); int r_ = idx_ >> 2, c4_ = idx_ & 3; \
    int mf_ = r_ >> 4, g_ = r_ & 7, sl_ = ((r_ >> 3) & 1) + 2*(c4_ & 1); int kk_ = c4_ >> 1; \
    As[buf][mf_][kk_][g_*4+0][sl_] = f2tf((v).x); As[buf][mf_][kk_][g_*4+1][sl_] = f2tf((v).y); \
    As[buf][mf_][kk_][g_*4+2][sl_] = f2tf((v).z); As[buf][mf_][kk_][g_*4+3][sl_] = f2tf((v).w); }
#define STB(buf, i, v) { int idx_ = tid + 256*(i); int n_ = idx_ >> 2, c4_ = idx_ & 3; \
    int nf_ = n_ >> 3, g_ = n_ & 7, sl_ = c4_ & 1; int kk_ = c4_ >> 1; \
    Bs[buf][nf_][kk_][g_*4+0][sl_] = f2tf((v).x); Bs[buf][nf_][kk_][g_*4+1][sl_] = f2tf((v).y); \
    Bs[buf][nf_][kk_][g_*4+2][sl_] = f2tf((v).z); Bs[buf][nf_][kk_][g_*4+3][sl_] = f2tf((v).w); }

    pa0 = GLDA(0, 0); pa1 = GLDA(0, 1);
    pb0 = GLDB(0, 0); pb1 = GLDB(0, 1);
    STA(0, 0, pa0); STA(0, 1, pa1);
    STB(0, 0, pb0); STB(0, 1, pb1);
    __syncthreads();

    int nit = K >> 4, buf = 0;
    for (int it = 0; it < nit; it++) {
        bool more = (it + 1) < nit;
        if (more) {
            int k0 = (it + 1) << 4;
            pa0 = GLDA(k0, 0); pa1 = GLDA(k0, 1);
            pb0 = GLDB(k0, 0); pb1 = GLDB(k0, 1);
        }
#pragma unroll
        for (int kk = 0; kk < 2; kk++) {
            uint32_t av[4][4], bv[4][2];
#pragma unroll
            for (int mi = 0; mi < 4; mi++)
                *(uint4*)av[mi] = *(const uint4*)&As[buf][wm*4 + mi][kk][lane][0];
#pragma unroll
            for (int ni = 0; ni < 4; ni++)
                *(uint2*)bv[ni] = *(const uint2*)&Bs[buf][wn*4 + ni][kk][lane][0];
#pragma unroll
            for (int mi = 0; mi < 4; mi++)
#pragma unroll
                for (int ni = 0; ni < 4; ni++)
                    mma8(acc[mi][ni], av[mi], bv[ni]);
        }
        if (more) {
            STA(buf ^ 1, 0, pa0); STA(buf ^ 1, 1, pa1);
            STB(buf ^ 1, 0, pb0); STB(buf ^ 1, 1, pb1);
        }
        __syncthreads();
        buf ^= 1;
    }
#undef GLDA
#undef GLDB
#undef STA
#undef STB
    int g = lane >> 2, tig = lane & 3;
#pragma unroll
    for (int mi = 0; mi < 4; mi++) {
        int r1 = m0 + wm*64 + mi*16 + g;
        int r2 = r1 + 8;
#pragma unroll
        for (int ni = 0; ni < 4; ni++) {
            int c = n0 + wn*32 + ni*8 + 2*tig;
            float2 v1 = make_float2(acc[mi][ni][0], acc[mi][ni][1]);
            float2 v2 = make_float2(acc[mi][ni][2], acc[mi][ni][3]);
            if (R) {
                float2 q1 = *(const float2*)(R + (size_t)r1 * N + c);
                float2 q2 = *(const float2*)(R + (size_t)r2 * N + c);
                v1.x += q1.x; v1.y += q1.y; v2.x += q2.x; v2.y += q2.y;
            }
            *(float2*)(C + (size_t)r1 * N + c) = v1;
            *(float2*)(C + (size_t)r2 * N + c) = v2;
        }
    }
}

// =====================================================================
// MoE GEMM1 (tf32 mma): act = silu(h@w1^T) * (h@w3^T), gathered rows
// CTA tile 128x64x16 with TWO B matrices; warps 64x16
// =====================================================================
__global__ __launch_bounds__(256) void k_mma_moe1(const float* __restrict__ h2,
                                                   const float* __restrict__ w1,
                                                   const float* __restrict__ w3) {
    int e = blockIdx.z;
    int cnt = g_cnt[e];
    int m0 = blockIdx.y * 128;
    if (m0 >= cnt) return;
    int off = g_off[e];
    int n0 = blockIdx.x * 64;
    const float* B1 = w1 + (size_t)e * Fn * Dn;
    const float* B3 = w3 + (size_t)e * Fn * Dn;

    __shared__ uint32_t As[2][8][2][32][4];
    __shared__ uint32_t B1s[2][8][2][32][2];
    __shared__ uint32_t B3s[2][8][2][32][2];
    __shared__ int toks[128];
    int tid = threadIdx.x;
    if (tid < 128) toks[tid] = (m0 + tid < cnt) ? g_list_tok[off + m0 + tid] : g_list_tok[off];
    __syncthreads();

    int lane = tid & 31, w = tid >> 5, wm = w >> 2, wn = w & 3;
    float aU[4][2][4] = {}, aG[4][2][4] = {};
    float4 pa0, pa1, pb1, pb3;

#define GLDA(k0, i) (*(const float4*)(h2 + (size_t)toks[(tid + 256*(i)) >> 2] * Dn + (k0) + ((tid + 256*(i)) & 3) * 4))
#define GLD1(k0) (*(const float4*)(B1 + (size_t)(n0 + (tid >> 2)) * Dn + (k0) + (tid & 3) * 4))
#define GLD3(k0) (*(const float4*)(B3 + (size_t)(n0 + (tid >> 2)) * Dn + (k0) + (tid & 3) * 4))
#define STA(buf, i, v) { int idx_ = tid + 256*(i); int r_ = idx_ >> 2, c4_ = idx_ & 3; \
    int mf_ = r_ >> 4, g_ = r_ & 7, sl_ = ((r_ >> 3) & 1) + 2*(c4_ & 1); int kk_ = c4_ >> 1; \
    As[buf][mf_][kk_][g_*4+0][sl_] = f2tf((v).x); As[buf][mf_][kk_][g_*4+1][sl_] = f2tf((v).y); \
    As[buf][mf_][kk_][g_*4+2][sl_] = f2tf((v).z); As[buf][mf_][kk_][g_*4+3][sl_] = f2tf((v).w); }
#define STB(arr, buf, v) { int n_ = tid >> 2, c4_ = tid & 3; \
    int nf_ = n_ >> 3, g_ = n_ & 7, sl_ = c4_ & 1; int kk_ = c4_ >> 1; \
    arr[buf][nf_][kk_][g_*4+0][sl_] = f2tf((v).x); arr[buf][nf_][kk_][g_*4+1][sl_] = f2tf((v).y); \
    arr[buf][nf_][kk_][g_*4+2][sl_] = f2tf((v).z); arr[buf][nf_][kk_][g_*4+3][sl_] = f2tf((v).w); }

    pa0 = GLDA(0, 0); pa1 = GLDA(0, 1); pb1 = GLD1(0); pb3 = GLD3(0);
    STA(0, 0, pa0); STA(0, 1, pa1);
    STB(B1s, 0, pb1); STB(B3s, 0, pb3);
    __syncthreads();

    int nit = Dn >> 4, buf = 0;
    for (int it = 0; it < nit; it++) {
        bool more = (it + 1) < nit;
        if (more) {
            int k0 = (it + 1) << 4;
            pa0 = GLDA(k0, 0); pa1 = GLDA(k0, 1);
            pb1 = GLD1(k0); pb3 = GLD3(k0);
        }
#pragma unroll
        for (int kk = 0; kk < 2; kk++) {
            uint32_t av[4][4], b1v[2][2], b3v[2][2];
#pragma unroll
            for (int mi = 0; mi < 4; mi++)
                *(uint4*)av[mi] = *(const uint4*)&As[buf][wm*4 + mi][kk][lane][0];
#pragma unroll
            for (int ni = 0; ni < 2; ni++) {
                *(uint2*)b1v[ni] = *(const uint2*)&B1s[buf][wn*2 + ni][kk][lane][0];
                *(uint2*)b3v[ni] = *(const uint2*)&B3s[buf][wn*2 + ni][kk][lane][0];
            }
#pragma unroll
            for (int mi = 0; mi < 4; mi++)
#pragma unroll
                for (int ni = 0; ni < 2; ni++) {
                    mma8(aU[mi][ni], av[mi], b1v[ni]);
                    mma8(aG[mi][ni], av[mi], b3v[ni]);
                }
        }
        if (more) {
            STA(buf ^ 1, 0, pa0); STA(buf ^ 1, 1, pa1);
            STB(B1s, buf ^ 1, pb1); STB(B3s, buf ^ 1, pb3);
        }
        __syncthreads();
        buf ^= 1;
    }
#undef GLDA
#undef GLD1
#undef GLD3
#undef STA
#undef STB
    int g = lane >> 2, tig = lane & 3;
#pragma unroll
    for (int mi = 0; mi < 4; mi++) {
#pragma unroll
        for (int half = 0; half < 2; half++) {
            int r = m0 + wm*64 + mi*16 + g + half*8;
            if (r >= cnt) continue;
            float* dst = g_act + (size_t)(off + r) * Fn;
#pragma unroll
            for (int ni = 0; ni < 2; ni++) {
                int c = n0 + wn*16 + ni*8 + 2*tig;
                float u0 = aU[mi][ni][half*2+0], g0 = aG[mi][ni][half*2+0];
                float u1 = aU[mi][ni][half*2+1], g1 = aG[mi][ni][half*2+1];
                float s0 = u0 / (1.f + expf(-u0)) * g0;
                float s1 = u1 / (1.f + expf(-u1)) * g1;
                *(float2*)(dst + c) = make_float2(s0, s1);
            }
        }
    }
}

// =====================================================================
// MoE GEMM2 (tf32 mma): ffn = act @ w2^T  (dense compact rows, K=Fn)
// =====================================================================
__global__ __launch_bounds__(256) void k_mma_moe2(const float* __restrict__ w2) {
    int e = blockIdx.z;
    int cnt = g_cnt[e];
    int m0 = blockIdx.y * 128;
    if (m0 >= cnt) return;
    int off = g_off[e];
    int n0 = blockIdx.x * 128;
    const float* A = g_act + (size_t)off * Fn;
    const float* B = w2 + (size_t)e * Dn * Fn;

    __shared__ uint32_t As[2][8][2][32][4];
    __shared__ uint32_t Bs[2][16][2][32][2];
    int tid = threadIdx.x;
    int lane = tid & 31, w = tid >> 5, wm = w >> 2, wn = w & 3;
    float acc[4][4][4] = {};
    float4 pa0, pa1, pb0, pb1;

#define ARow(i) min(m0 + ((tid + 256*(i)) >> 2), cnt - 1)
#define GLDA(k0, i) (*(const float4*)(A + (size_t)ARow(i) * Fn + (k0) + ((tid + 256*(i)) & 3) * 4))
#define GLDB(k0, i) (*(const float4*)(B + (size_t)(n0 + ((tid + 256*(i)) >> 2)) * Fn + (k0) + ((tid + 256*(i)) & 3) * 4))
#define STA(buf, i, v) { int idx_ = tid + 256*(i); int r_ = idx_ >> 2, c4_ = idx_ & 3; \
    int mf_ = r_ >> 4, g_ = r_ & 7, sl_ = ((r_ >> 3) & 1) + 2*(c4_ & 1); int kk_ = c4_ >> 1; \
    As[buf][mf_][kk_][g_*4+0][sl_] = f2tf((v).x); As[buf][mf_][kk_][g_*4+1][sl_] = f2tf((v).y); \
    As[buf][mf_][kk_][g_*4+2][sl_] = f2tf((v).z); As[buf][mf_][kk_][g_*4+3][sl_] = f2tf((v).w); }
#define STB(buf, i, v) { int idx_ = tid + 256*(i); int n_ = idx_ >> 2, c4_ = idx_ & 3; \
    int nf_ = n_ >> 3, g_ = n_ & 7, sl_ = c4_ & 1; int kk_ = c4_ >> 1; \
    Bs[buf][nf_][kk_][g_*4+0][sl_] = f2tf((v).x); Bs[buf][nf_][kk_][g_*4+1][sl_] = f2tf((v).y); \
    Bs[buf][nf_][kk_][g_*4+2][sl_] = f2tf((v).z); Bs[buf][nf_][kk_][g_*4+3][sl_] = f2tf((v).w); }

    pa0 = GLDA(0, 0); pa1 = GLDA(0, 1);
    pb0 = GLDB(0, 0); pb1 = GLDB(0, 1);
    STA(0, 0, pa0); STA(0, 1, pa1);
    STB(0, 0, pb0); STB(0, 1, pb1);
    __syncthreads();

    int nit = Fn >> 4, buf = 0;
    for (int it = 0; it < nit; it++) {
        bool more = (it + 1) < nit;
        if (more) {
            int k0 = (it + 1) << 4;
            pa0 = GLDA(k0, 0); pa1 = GLDA(k0, 1);
            pb0 = GLDB(k0, 0); pb1 = GLDB(k0, 1);
        }
#pragma unroll
        for (int kk = 0; kk < 2; kk++) {
            uint32_t av[4][4], bv[4][2];
#pragma unroll
            for (int mi = 0; mi < 4; mi++)
                *(uint4*)av[mi] = *(const uint4*)&As[buf][wm*4 + mi][kk][lane][0];
#pragma unroll
            for (int ni = 0; ni < 4; ni++)
                *(uint2*)bv[ni] = *(const uint2*)&Bs[buf][wn*4 + ni][kk][lane][0];
#pragma unroll
            for (int mi = 0; mi < 4; mi++)
#pragma unroll
                for (int ni = 0; ni < 4; ni++)
                    mma8(acc[mi][ni], av[mi], bv[ni]);
        }
        if (more) {
            STA(buf ^ 1, 0, pa0); STA(buf ^ 1, 1, pa1);
            STB(buf ^ 1, 0, pb0); STB(buf ^ 1, 1, pb1);
        }
        __syncthreads();
        buf ^= 1;
    }
#undef ARow
#undef GLDA
#undef GLDB
#undef STA
#undef STB
    int g = lane >> 2, tig = lane & 3;
#pragma unroll
    for (int mi = 0; mi < 4; mi++) {
        int r1 = m0 + wm*64 + mi*16 + g;
        int r2 = r1 + 8;
#pragma unroll
        for (int ni = 0; ni < 4; ni++) {
            int c = n0 + wn*32 + ni*8 + 2*tig;
            if (r1 < cnt)
                *(float2*)(g_ffn + (size_t)(off + r1) * Dn + c) = make_float2(acc[mi][ni][0], acc[mi][ni][1]);
            if (r2 < cnt)
                *(float2*)(g_ffn + (size_t)(off + r2) * Dn + c) = make_float2(acc[mi][ni][2], acc[mi][ni][3]);
        }
    }
}

// ---------------- RoPE (in place on q,k; layout (T, H*HD)) ----------------
__global__ void k_rope(float* __restrict__ q, float* __restrict__ k) {
    int gid = blockIdx.x * 256 + threadIdx.x;
    if (gid >= Tn * Hn * 64) return;
    int i = gid & 63;
    int h = (gid >> 6) & (Hn - 1);
    int t = gid >> 10;
    int s = t & (Sn - 1);
    float inv = powf(10000.0f, -(float)i / 64.0f);
    float ang = (float)s * inv;
    float sn, c;
    sincosf(ang, &sn, &c);
    size_t base = (size_t)t * Dn + h * HDn;
    float q1 = q[base + i], q2 = q[base + i + 64];
    q[base + i]      = q1 * c - q2 * sn;
    q[base + i + 64] = q2 * c + q1 * sn;
    float k1 = k[base + i], k2 = k[base + i + 64];
    k[base + i]      = k1 * c - k2 * sn;
    k[base + i + 64] = k2 * c + k1 * sn;
}

// ---------------- causal attention, flash-style 64x64 tiles, fp32 ----------------
#define ATTN_SMEM_FLOATS (64*128 + 64*129 + 64*64 + 64*3)
__global__ __launch_bounds__(256) void k_attn(const float* __restrict__ q,
                                              const float* __restrict__ k,
                                              const float* __restrict__ v,
                                              float* __restrict__ ctx) {
    extern __shared__ float sm[];
    float* Qs   = sm;
    float* KVs  = Qs + 64 * 128;
    float* Ss   = KVs + 64 * 129;
    float* m_s  = Ss + 4096;
    float* l_s  = m_s + 64;
    float* al_s = l_s + 64;
    int tid = threadIdx.x;
    int qt = blockIdx.x;
    int bh = blockIdx.y;
    int b = bh >> 4, h = bh & 15;
    const float scale = 0.08838834764831845f;

    for (int idx = tid; idx < 64 * 128; idx += 256) {
        int r = idx >> 7, c = idx & 127;
        Qs[idx] = q[(size_t)(b * Sn + qt * 64 + r) * Dn + h * HDn + c];
    }
    if (tid < 64) { m_s[tid] = -1e30f; l_s[tid] = 0.f; }
    float acc[8][4] = {};
    int tx = tid & 31, ty = tid >> 5;

    for (int kt = 0; kt <= qt; kt++) {
        __syncthreads();
        for (int idx = tid; idx < 64 * 128; idx += 256) {
            int r = idx >> 7, c = idx & 127;
            KVs[r * 129 + c] = k[(size_t)(b * Sn + kt * 64 + r) * Dn + h * HDn + c];
        }
        __syncthreads();
        for (int idx = tid; idx < 4096; idx += 256) {
            int r = idx >> 6, j = idx & 63;
            const float* qp = Qs + r * 128;
            const float* kp = KVs + j * 129;
            float s = 0.f;
#pragma unroll 16
            for (int kk = 0; kk < 128; kk++) s += qp[kk] * kp[kk];
            s *= scale;
            if (kt * 64 + j > qt * 64 + r) s = -1e30f;
            Ss[idx] = s;
        }
        __syncthreads();
        if (tid < 64) {
            int r = tid;
            float* sr = Ss + r * 64;
            float mo = m_s[r], tm = -1e30f;
            for (int j = 0; j < 64; j++) tm = fmaxf(tm, sr[j]);
            float nm = fmaxf(mo, tm);
            float a = expf(mo - nm);
            float sum = 0.f;
            for (int j = 0; j < 64; j++) { float p = expf(sr[j] - nm); sr[j] = p; sum += p; }
            l_s[r] = l_s[r] * a + sum;
            m_s[r] = nm;
            al_s[r] = a;
        }
        __syncthreads();
        for (int idx = tid; idx < 64 * 128; idx += 256) {
            int r = idx >> 7, c = idx & 127;
            KVs[r * 129 + c] = v[(size_t)(b * Sn + kt * 64 + r) * Dn + h * HDn + c];
        }
        __syncthreads();
#pragma unroll
        for (int i = 0; i < 8; i++) {
            int r = ty * 8 + i;
            float a = al_s[r];
            const float* pr = Ss + r * 64;
            float c0 = acc[i][0] * a, c1 = acc[i][1] * a;
            float c2 = acc[i][2] * a, c3 = acc[i][3] * a;
            for (int j = 0; j < 64; j++) {
                float p = pr[j];
                const float* vp = KVs + j * 129 + tx;
                c0 += p * vp[0];
                c1 += p * vp[32];
                c2 += p * vp[64];
                c3 += p * vp[96];
            }
            acc[i][0] = c0; acc[i][1] = c1; acc[i][2] = c2; acc[i][3] = c3;
        }
    }
#pragma unroll
    for (int i = 0; i < 8; i++) {
        int r = ty * 8 + i;
        float invl = 1.f / l_s[r];
        size_t base = (size_t)(b * Sn + qt * 64 + r) * Dn + h * HDn + tx;
        ctx[base]      = acc[i][0] * invl;
        ctx[base + 32] = acc[i][1] * invl;
        ctx[base + 64] = acc[i][2] * invl;
        ctx[base + 96] = acc[i][3] * invl;
    }
}

// ---------------- MoE routing ----------------
__global__ void k_zero() { if (threadIdx.x < En) g_cnt[threadIdx.x] = 0; }

__global__ void k_route(const float* __restrict__ h2, const float* __restrict__ gw) {
    int t = blockIdx.x;
    int lane = threadIdx.x & 31, wid = threadIdx.x >> 5;
    const float* hr = h2 + (size_t)t * Dn;
    const float* gr = gw + (size_t)wid * Dn;
    float s = 0.f;
    for (int i = lane; i < Dn; i += 32) s += hr[i] * gr[i];
    for (int o = 16; o; o >>= 1) s += __shfl_down_sync(0xffffffffu, s, o);
    __shared__ float lg[En];
    if (lane == 0) lg[wid] = s;
    __syncthreads();
    if (threadIdx.x == 0) {
        float mx = lg[0];
        for (int e = 1; e < En; e++) mx = fmaxf(mx, lg[e]);
        float p[En];
        for (int e = 0; e < En; e++) p[e] = expf(lg[e] - mx);
        int i1 = 0;
        for (int e = 1; e < En; e++) if (p[e] > p[i1]) i1 = e;
        int i2 = (i1 == 0) ? 1 : 0;
        for (int e = 0; e < En; e++) { if (e == i1) continue; if (p[e] > p[i2]) i2 = e; }
        float norm = p[i1] + p[i2];
        g_tok_e[t * 2]     = i1; g_tok_w[t * 2]     = p[i1] / norm;
        g_tok_e[t * 2 + 1] = i2; g_tok_w[t * 2 + 1] = p[i2] / norm;
        atomicAdd(&g_cnt[i1], 1);
        atomicAdd(&g_cnt[i2], 1);
    }
}

__global__ void k_scan() {
    if (threadIdx.x == 0) {
        int o = 0;
        for (int e = 0; e < En; e++) { g_off[e] = o; o += g_cnt[e]; g_run[e] = 0; }
    }
}

__global__ void k_place() {
    int t = blockIdx.x * 256 + threadIdx.x;
    if (t >= Tn) return;
    for (int kk = 0; kk < KKn; kk++) {
        int e = g_tok_e[t * 2 + kk];
        int pos = g_off[e] + atomicAdd(&g_run[e], 1);
        g_list_tok[pos] = t;
        g_tok_pos[t * 2 + kk] = pos;
    }
}

// ---------------- final: out = x1 + w0*ffn[p0] + w1*ffn[p1] ----------------
__global__ void k_final(float* __restrict__ out) {
    int t = blockIdx.x;
    int p0 = g_tok_pos[t * 2], p1 = g_tok_pos[t * 2 + 1];
    float w0 = g_tok_w[t * 2], w1 = g_tok_w[t * 2 + 1];
    const float4* x1 = (const float4*)(g_x1 + (size_t)t * Dn);
    const float4* f0 = (const float4*)(g_ffn + (size_t)p0 * Dn);
    const float4* f1 = (const float4*)(g_ffn + (size_t)p1 * Dn);
    float4* o = (float4*)(out + (size_t)t * Dn);
    for (int c = threadIdx.x; c < Dn / 4; c += 256) {
        float4 a = x1[c], b = f0[c], d = f1[c];
        a.x += w0 * b.x + w1 * d.x;
        a.y += w0 * b.y + w1 * d.y;
        a.z += w0 * b.z + w1 * d.z;
        a.w += w0 * b.w + w1 * d.w;
        o[c] = a;
    }
}

extern "C" void kernel_launch(void* const* d_in, const int* in_sizes, int n_in,
                              void* d_out, int out_size) {
    (void)in_sizes; (void)n_in; (void)out_size;
    const float* x   = (const float*)d_in[0];
    const float* ln1 = (const float*)d_in[3];
    const float* wq  = (const float*)d_in[4];
    const float* wk  = (const float*)d_in[5];
    const float* wv  = (const float*)d_in[6];
    const float* wo  = (const float*)d_in[7];
    const float* ln2 = (const float*)d_in[8];
    const float* gw  = (const float*)d_in[9];
    const float* w1  = (const float*)d_in[10];
    const float* w3  = (const float*)d_in[11];
    const float* w2  = (const float*)d_in[12];
    float* out = (float*)d_out;

    float *h1, *qb, *kb, *vb, *cb, *x1b, *h2b;
    cudaGetSymbolAddress((void**)&h1,  g_h1);
    cudaGetSymbolAddress((void**)&qb,  g_q);
    cudaGetSymbolAddress((void**)&kb,  g_k);
    cudaGetSymbolAddress((void**)&vb,  g_v);
    cudaGetSymbolAddress((void**)&cb,  g_ctx);
    cudaGetSymbolAddress((void**)&x1b, g_x1);
    cudaGetSymbolAddress((void**)&h2b, g_h2);

    const int smem_attn = ATTN_SMEM_FLOATS * 4;
    cudaFuncSetAttribute(k_attn, cudaFuncAttributeMaxDynamicSharedMemorySize, smem_attn);

    // 1. RMSNorm 1
    k_rmsnorm<<<Tn, 256>>>(x, ln1, h1);
    // 2. QKV projections (tf32 tensor cores)
    dim3 g1(Dn / 128, Tn / 128);
    k_mma_gemm<<<g1, 256>>>(h1, wq, nullptr, qb, Tn, Dn, Dn);
    k_mma_gemm<<<g1, 256>>>(h1, wk, nullptr, kb, Tn, Dn, Dn);
    k_mma_gemm<<<g1, 256>>>(h1, wv, nullptr, vb, Tn, Dn, Dn);
    // 3. RoPE
    k_rope<<<(Tn * Hn * 64) / 256, 256>>>(qb, kb);
    // 4. attention (fp32 flash)
    dim3 ga(Sn / 64, Bn * Hn);
    k_attn<<<ga, 256, smem_attn>>>(qb, kb, vb, cb);
    // 5. O projection + residual (tf32)
    k_mma_gemm<<<g1, 256>>>(cb, wo, x, x1b, Tn, Dn, Dn);
    // 6. RMSNorm 2
    k_rmsnorm<<<Tn, 256>>>(x1b, ln2, h2b);
    // 7. routing
    k_zero<<<1, 32>>>();
    k_route<<<Tn, 256>>>(h2b, gw);
    k_scan<<<1, 32>>>();
    k_place<<<Tn / 256, 256>>>();
    // 8. MoE expert GEMMs (tf32)
    dim3 gm1(Fn / 64, Tn / 128, En);
    k_mma_moe1<<<gm1, 256>>>(h2b, w1, w3);
    dim3 gm2(Dn / 128, Tn / 128, En);
    k_mma_moe2<<<gm2, 256>>>(w2);
    // 9. combine
    k_final<<<Tn, 256>>>(out);
}

// round 3
// speedup vs baseline: 2.2215x; 1.0026x over previous
#include <cuda_runtime.h>
#include <math.h>
#include <stdint.h>

#define Bn 2
#define Sn 2048
#define Dn 2048
#define Hn 16
#define HDn 128
#define Tn (Bn*Sn)      // 4096 tokens
#define En 8
#define KKn 2
#define Fn 4096

// ---------------- scratch (device globals; no runtime allocation) ----------------
__device__ float g_h1[Tn*Dn];
__device__ float g_q[Tn*Dn];
__device__ float g_k[Tn*Dn];
__device__ float g_v[Tn*Dn];
__device__ float g_ctx[Tn*Dn];
__device__ float g_x1[Tn*Dn];
__device__ float g_h2[Tn*Dn];
__device__ float g_act[(size_t)Tn*KKn*Fn];   // compact (token,expert) activation rows
__device__ float g_ffn[(size_t)Tn*KKn*Dn];   // expert FFN outputs (compact rows)
__device__ int   g_cnt[En];
__device__ int   g_off[En];
__device__ int   g_run[En];
__device__ int   g_tok_e[Tn*KKn];
__device__ float g_tok_w[Tn*KKn];
__device__ int   g_tok_pos[Tn*KKn];
__device__ int   g_list_tok[Tn*KKn];

__device__ __forceinline__ uint32_t f2tf(float f) {
    uint32_t u;
    asm("cvt.rna.tf32.f32 %0, %1;" : "=r"(u) : "f"(f));
    return u;
}

__device__ __forceinline__ void mma8(float* d, const uint32_t* a, const uint32_t* b) {
    asm volatile(
        "mma.sync.aligned.m16n8k8.row.col.f32.tf32.tf32.f32 "
        "{%0,%1,%2,%3}, {%4,%5,%6,%7}, {%8,%9}, {%0,%1,%2,%3};"
        : "+f"(d[0]), "+f"(d[1]), "+f"(d[2]), "+f"(d[3])
        : "r"(a[0]), "r"(a[1]), "r"(a[2]), "r"(a[3]), "r"(b[0]), "r"(b[1]));
}

// ---------------- RMSNorm ----------------
__global__ void k_rmsnorm(const float* __restrict__ x, const float* __restrict__ w,
                          float* __restrict__ out) {
    int row = blockIdx.x;
    const float* xr = x + (size_t)row * Dn;
    float ss = 0.f;
    for (int i = threadIdx.x; i < Dn; i += 256) { float v = xr[i]; ss += v * v; }
    __shared__ float sh[256];
    sh[threadIdx.x] = ss;
    __syncthreads();
    for (int o = 128; o > 0; o >>= 1) {
        if (threadIdx.x < o) sh[threadIdx.x] += sh[threadIdx.x + o];
        __syncthreads();
    }
    float inv = rsqrtf(sh[0] / (float)Dn + 1e-6f);
    float* orow = out + (size_t)row * Dn;
    for (int i = threadIdx.x; i < Dn; i += 256) orow[i] = xr[i] * inv * w[i];
}

// =====================================================================
// tf32 tensor-core GEMM: C(MxN) = A(MxK) @ B(NxK)^T (+ optional residual)
// CTA tile 128x128x16, 8 warps of 64x32, double-buffered fragment-major smem
// =====================================================================
__global__ __launch_bounds__(256) void k_mma_gemm(const float* __restrict__ A,
                                                  const float* __restrict__ B,
                                                  const float* __restrict__ R,
                                                  float* __restrict__ C,
                                                  int M, int N, int K) {
    __shared__ uint32_t As[2][8][2][32][4];   // [buf][mfrag][kk8][lane][slot]
    __shared__ uint32_t Bs[2][16][2][32][2];  // [buf][nfrag][kk8][lane][slot]
    int tid = threadIdx.x;
    int m0 = blockIdx.y * 128, n0 = blockIdx.x * 128;
    int lane = tid & 31, w = tid >> 5, wm = w >> 2, wn = w & 3;
    float acc[4][4][4] = {};
    float4 pa0, pa1, pb0, pb1;

#define GLDA(k0, i) (*(const float4*)(A + (size_t)(m0 + ((tid + 256*(i)) >> 2)) * K + (k0) + ((tid + 256*(i)) & 3) * 4))
#define GLDB(k0, i) (*(const float4*)(B + (size_t)(n0 + ((tid + 256*(i)) >> 2)) * K + (k0) + ((tid + 256*(i)) & 3) * 4))
#define STA(buf, i, v) { int idx_ = tid + 256*(i); int r_ = idx_ >> 2, c4_ = idx_ & 3; \
    int mf_ = r_ >> 4, g_ = r_ & 7, sl_ = ((r_ >> 3) & 1) + 2*(c4_ & 1); int kk_ = c4_ >> 1; \
    As[buf][mf_][kk_][g_*4+0][sl_] = f2tf((v).x); As[buf][mf_][kk_][g_*4+1][sl_] = f2tf((v).y); \
    As[buf][mf_][kk_][g_*4+2][sl_] = f2tf((v).z); As[buf][mf_][kk_][g_*4+3][sl_] = f2tf((v).w); }
#define STB(buf, i, v) { int idx_ = tid + 256*(i); int n_ = idx_ >> 2, c4_ = idx_ & 3; \
    int nf_ = n_ >> 3, g_ = n_ & 7, sl_ = c4_ & 1; int kk_ = c4_ >> 1; \
    Bs[buf][nf_][kk_][g_*4+0][sl_] = f2tf((v).x); Bs[buf][nf_][kk_][g_*4+1][sl_] = f2tf((v).y); \
    Bs[buf][nf_][kk_][g_*4+2][sl_] = f2tf((v).z); Bs[buf][nf_][kk_][g_*4+3][sl_] = f2tf((v).w); }

    pa0 = GLDA(0, 0); pa1 = GLDA(0, 1);
    pb0 = GLDB(0, 0); pb1 = GLDB(0, 1);
    STA(0, 0, pa0); STA(0, 1, pa1);
    STB(0, 0, pb0); STB(0, 1, pb1);
    __syncthreads();

    int nit = K >> 4, buf = 0;
    for (int it = 0; it < nit; it++) {
        bool more = (it + 1) < nit;
        if (more) {
            int k0 = (it + 1) << 4;
            pa0 = GLDA(k0, 0); pa1 = GLDA(k0, 1);
            pb0 = GLDB(k0, 0); pb1 = GLDB(k0, 1);
        }
#pragma unroll
        for (int kk = 0; kk < 2; kk++) {
            uint32_t av[4][4], bv[4][2];
#pragma unroll
            for (int mi = 0; mi < 4; mi++)
                *(uint4*)av[mi] = *(const uint4*)&As[buf][wm*4 + mi][kk][lane][0];
#pragma unroll
            for (int ni = 0; ni < 4; ni++)
                *(uint2*)bv[ni] = *(const uint2*)&Bs[buf][wn*4 + ni][kk][lane][0];
#pragma unroll
            for (int mi = 0; mi < 4; mi++)
#pragma unroll
                for (int ni = 0; ni < 4; ni++)
                    mma8(acc[mi][ni], av[mi], bv[ni]);
        }
        if (more) {
            STA(buf ^ 1, 0, pa0); STA(buf ^ 1, 1, pa1);
            STB(buf ^ 1, 0, pb0); STB(buf ^ 1, 1, pb1);
        }
        __syncthreads();
        buf ^= 1;
    }
#undef GLDA
#undef GLDB
#undef STA
#undef STB
    int g = lane >> 2, tig = lane & 3;
#pragma unroll
    for (int mi = 0; mi < 4; mi++) {
        int r1 = m0 + wm*64 + mi*16 + g;
        int r2 = r1 + 8;
#pragma unroll
        for (int ni = 0; ni < 4; ni++) {
            int c = n0 + wn*32 + ni*8 + 2*tig;
            float2 v1 = make_float2(acc[mi][ni][0], acc[mi][ni][1]);
            float2 v2 = make_float2(acc[mi][ni][2], acc[mi][ni][3]);
            if (R) {
                float2 q1 = *(const float2*)(R + (size_t)r1 * N + c);
                float2 q2 = *(const float2*)(R + (size_t)r2 * N + c);
                v1.x += q1.x; v1.y += q1.y; v2.x += q2.x; v2.y += q2.y;
            }
            *(float2*)(C + (size_t)r1 * N + c) = v1;
            *(float2*)(C + (size_t)r2 * N + c) = v2;
        }
    }
}

// =====================================================================
// MoE GEMM1 (tf32 mma): act = silu(h@w1^T) * (h@w3^T), gathered rows
// CTA tile 128x64x16 with TWO B matrices; warps 64x16
// =====================================================================
__global__ __launch_bounds__(256) void k_mma_moe1(const float* __restrict__ h2,
                                                   const float* __restrict__ w1,
                                                   const float* __restrict__ w3) {
    int e = blockIdx.z;
    int cnt = g_cnt[e];
    int m0 = blockIdx.y * 128;
    if (m0 >= cnt) return;
    int off = g_off[e];
    int n0 = blockIdx.x * 64;
    const float* B1 = w1 + (size_t)e * Fn * Dn;
    const float* B3 = w3 + (size_t)e * Fn * Dn;

    __shared__ uint32_t As[2][8][2][32][4];
    __shared__ uint32_t B1s[2][8][2][32][2];
    __shared__ uint32_t B3s[2][8][2][32][2];
    __shared__ int toks[128];
    int tid = threadIdx.x;
    if (tid < 128) toks[tid] = (m0 + tid < cnt) ? g_list_tok[off + m0 + tid] : g_list_tok[off];
    __syncthreads();

    int lane = tid & 31, w = tid >> 5, wm = w >> 2, wn = w & 3;
    float aU[4][2][4] = {}, aG[4][2][4] = {};
    float4 pa0, pa1, pb1, pb3;

#define GLDA(k0, i) (*(const float4*)(h2 + (size_t)toks[(tid + 256*(i)) >> 2] * Dn + (k0) + ((tid + 256*(i)) & 3) * 4))
#define GLD1(k0) (*(const float4*)(B1 + (size_t)(n0 + (tid >> 2)) * Dn + (k0) + (tid & 3) * 4))
#define GLD3(k0) (*(const float4*)(B3 + (size_t)(n0 + (tid >> 2)) * Dn + (k0) + (tid & 3) * 4))
#define STA(buf, i, v) { int idx_ = tid + 256*(i); int r_ = idx_ >> 2, c4_ = idx_ & 3; \
    int mf_ = r_ >> 4, g_ = r_ & 7, sl_ = ((r_ >> 3) & 1) + 2*(c4_ & 1); int kk_ = c4_ >> 1; \
    As[buf][mf_][kk_][g_*4+0][sl_] = f2tf((v).x); As[buf][mf_][kk_][g_*4+1][sl_] = f2tf((v).y); \
    As[buf][mf_][kk_][g_*4+2][sl_] = f2tf((v).z); As[buf][mf_][kk_][g_*4+3][sl_] = f2tf((v).w); }
#define STB(arr, buf, v) { int n_ = tid >> 2, c4_ = tid & 3; \
    int nf_ = n_ >> 3, g_ = n_ & 7, sl_ = c4_ & 1; int kk_ = c4_ >> 1; \
    arr[buf][nf_][kk_][g_*4+0][sl_] = f2tf((v).x); arr[buf][nf_][kk_][g_*4+1][sl_] = f2tf((v).y); \
    arr[buf][nf_][kk_][g_*4+2][sl_] = f2tf((v).z); arr[buf][nf_][kk_][g_*4+3][sl_] = f2tf((v).w); }

    pa0 = GLDA(0, 0); pa1 = GLDA(0, 1); pb1 = GLD1(0); pb3 = GLD3(0);
    STA(0, 0, pa0); STA(0, 1, pa1);
    STB(B1s, 0, pb1); STB(B3s, 0, pb3);
    __syncthreads();

    int nit = Dn >> 4, buf = 0;
    for (int it = 0; it < nit; it++) {
        bool more = (it + 1) < nit;
        if (more) {
            int k0 = (it + 1) << 4;
            pa0 = GLDA(k0, 0); pa1 = GLDA(k0, 1);
            pb1 = GLD1(k0); pb3 = GLD3(k0);
        }
#pragma unroll
        for (int kk = 0; kk < 2; kk++) {
            uint32_t av[4][4], b1v[2][2], b3v[2][2];
#pragma unroll
            for (int mi = 0; mi < 4; mi++)
                *(uint4*)av[mi] = *(const uint4*)&As[buf][wm*4 + mi][kk][lane][0];
#pragma unroll
            for (int ni = 0; ni < 2; ni++) {
                *(uint2*)b1v[ni] = *(const uint2*)&B1s[buf][wn*2 + ni][kk][lane][0];
                *(uint2*)b3v[ni] = *(const uint2*)&B3s[buf][wn*2 + ni][kk][lane][0];
            }
#pragma unroll
            for (int mi = 0; mi < 4; mi++)
#pragma unroll
                for (int ni = 0; ni < 2; ni++) {
                    mma8(aU[mi][ni], av[mi], b1v[ni]);
                    mma8(aG[mi][ni], av[mi], b3v[ni]);
                }
        }
        if (more) {
            STA(buf ^ 1, 0, pa0); STA(buf ^ 1, 1, pa1);
            STB(B1s, buf ^ 1, pb1); STB(B3s, buf ^ 1, pb3);
        }
        __syncthreads();
        buf ^= 1;
    }
#undef GLDA
#undef GLD1
#undef GLD3
#undef STA
#undef STB
    int g = lane >> 2, tig = lane & 3;
#pragma unroll
    for (int mi = 0; mi < 4; mi++) {
#pragma unroll
        for (int half = 0; half < 2; half++) {
            int r = m0 + wm*64 + mi*16 + g + half*8;
            if (r >= cnt) continue;
            float* dst = g_act + (size_t)(off + r) * Fn;
#pragma unroll
            for (int ni = 0; ni < 2; ni++) {
                int c = n0 + wn*16 + ni*8 + 2*tig;
                float u0 = aU[mi][ni][half*2+0], g0 = aG[mi][ni][half*2+0];
                float u1 = aU[mi][ni][half*2+1], g1 = aG[mi][ni][half*2+1];
                float s0 = u0 / (1.f + expf(-u0)) * g0;
                float s1 = u1 / (1.f + expf(-u1)) * g1;
                *(float2*)(dst + c) = make_float2(s0, s1);
            }
        }
    }
}

// =====================================================================
// MoE GEMM2 (tf32 mma): ffn = act @ w2^T  (dense compact rows, K=Fn)
// =====================================================================
__global__ __launch_bounds__(256) void k_mma_moe2(const float* __restrict__ w2) {
    int e = blockIdx.z;
    int cnt = g_cnt[e];
    int m0 = blockIdx.y * 128;
    if (m0 >= cnt) return;
    int off = g_off[e];
    int n0 = blockIdx.x * 128;
    const float* A = g_act + (size_t)off * Fn;
    const float* B = w2 + (size_t)e * Dn * Fn;

    __shared__ uint32_t As[2][8][2][32][4];
    __shared__ uint32_t Bs[2][16][2][32][2];
    int tid = threadIdx.x;
    int lane = tid & 31, w = tid >> 5, wm = w >> 2, wn = w & 3;
    float acc[4][4][4] = {};
    float4 pa0, pa1, pb0, pb1;

#define ARow(i) min(m0 + ((tid + 256*(i)) >> 2), cnt - 1)
#define GLDA(k0, i) (*(const float4*)(A + (size_t)ARow(i) * Fn + (k0) + ((tid + 256*(i)) & 3) * 4))
#define GLDB(k0, i) (*(const float4*)(B + (size_t)(n0 + ((tid + 256*(i)) >> 2)) * Fn + (k0) + ((tid + 256*(i)) & 3) * 4))
#define STA(buf, i, v) { int idx_ = tid + 256*(i); int r_ = idx_ >> 2, c4_ = idx_ & 3; \
    int mf_ = r_ >> 4, g_ = r_ & 7, sl_ = ((r_ >> 3) & 1) + 2*(c4_ & 1); int kk_ = c4_ >> 1; \
    As[buf][mf_][kk_][g_*4+0][sl_] = f2tf((v).x); As[buf][mf_][kk_][g_*4+1][sl_] = f2tf((v).y); \
    As[buf][mf_][kk_][g_*4+2][sl_] = f2tf((v).z); As[buf][mf_][kk_][g_*4+3][sl_] = f2tf((v).w); }
#define STB(buf, i, v) { int idx_ = tid + 256*(i); int n_ = idx_ >> 2, c4_ = idx_ & 3; \
    int nf_ = n_ >> 3, g_ = n_ & 7, sl_ = c4_ & 1; int kk_ = c4_ >> 1; \
    Bs[buf][nf_][kk_][g_*4+0][sl_] = f2tf((v).x); Bs[buf][nf_][kk_][g_*4+1][sl_] = f2tf((v).y); \
    Bs[buf][nf_][kk_][g_*4+2][sl_] = f2tf((v).z); Bs[buf][nf_][kk_][g_*4+3][sl_] = f2tf((v).w); }

    pa0 = GLDA(0, 0); pa1 = GLDA(0, 1);
    pb0 = GLDB(0, 0); pb1 = GLDB(0, 1);
    STA(0, 0, pa0); STA(0, 1, pa1);
    STB(0, 0, pb0); STB(0, 1, pb1);
    __syncthreads();

    int nit = Fn >> 4, buf = 0;
    for (int it = 0; it < nit; it++) {
        bool more = (it + 1) < nit;
        if (more) {
            int k0 = (it + 1) << 4;
            pa0 = GLDA(k0, 0); pa1 = GLDA(k0, 1);
            pb0 = GLDB(k0, 0); pb1 = GLDB(k0, 1);
        }
#pragma unroll
        for (int kk = 0; kk < 2; kk++) {
            uint32_t av[4][4], bv[4][2];
#pragma unroll
            for (int mi = 0; mi < 4; mi++)
                *(uint4*)av[mi] = *(const uint4*)&As[buf][wm*4 + mi][kk][lane][0];
#pragma unroll
            for (int ni = 0; ni < 4; ni++)
                *(uint2*)bv[ni] = *(const uint2*)&Bs[buf][wn*4 + ni][kk][lane][0];
#pragma unroll
            for (int mi = 0; mi < 4; mi++)
#pragma unroll
                for (int ni = 0; ni < 4; ni++)
                    mma8(acc[mi][ni], av[mi], bv[ni]);
        }
        if (more) {
            STA(buf ^ 1, 0, pa0); STA(buf ^ 1, 1, pa1);
            STB(buf ^ 1, 0, pb0); STB(buf ^ 1, 1, pb1);
        }
        __syncthreads();
        buf ^= 1;
    }
#undef ARow
#undef GLDA
#undef GLDB
#undef STA
#undef STB
    int g = lane >> 2, tig = lane & 3;
#pragma unroll
    for (int mi = 0; mi < 4; mi++) {
        int r1 = m0 + wm*64 + mi*16 + g;
        int r2 = r1 + 8;
#pragma unroll
        for (int ni = 0; ni < 4; ni++) {
            int c = n0 + wn*32 + ni*8 + 2*tig;
            if (r1 < cnt)
                *(float2*)(g_ffn + (size_t)(off + r1) * Dn + c) = make_float2(acc[mi][ni][0], acc[mi][ni][1]);
            if (r2 < cnt)
                *(float2*)(g_ffn + (size_t)(off + r2) * Dn + c) = make_float2(acc[mi][ni][2], acc[mi][ni][3]);
        }
    }
}

// ---------------- RoPE (in place on q,k; layout (T, H*HD)) ----------------
__global__ void k_rope(float* __restrict__ q, float* __restrict__ k) {
    int gid = blockIdx.x * 256 + threadIdx.x;
    if (gid >= Tn * Hn * 64) return;
    int i = gid & 63;
    int h = (gid >> 6) & (Hn - 1);
    int t = gid >> 10;
    int s = t & (Sn - 1);
    float inv = powf(10000.0f, -(float)i / 64.0f);
    float ang = (float)s * inv;
    float sn, c;
    sincosf(ang, &sn, &c);
    size_t base = (size_t)t * Dn + h * HDn;
    float q1 = q[base + i], q2 = q[base + i + 64];
    q[base + i]      = q1 * c - q2 * sn;
    q[base + i + 64] = q2 * c + q1 * sn;
    float k1 = k[base + i], k2 = k[base + i + 64];
    k[base + i]      = k1 * c - k2 * sn;
    k[base + i + 64] = k2 * c + k1 * sn;
}

// ---------------- causal attention, flash-style 64x64 tiles, fp32 ----------------
#define ATTN_SMEM_FLOATS (64*128 + 64*129 + 64*64 + 64*3)
__global__ __launch_bounds__(256) void k_attn(const float* __restrict__ q,
                                              const float* __restrict__ k,
                                              const float* __restrict__ v,
                                              float* __restrict__ ctx) {
    extern __shared__ float sm[];
    float* Qs   = sm;
    float* KVs  = Qs + 64 * 128;
    float* Ss   = KVs + 64 * 129;
    float* m_s  = Ss + 4096;
    float* l_s  = m_s + 64;
    float* al_s = l_s + 64;
    int tid = threadIdx.x;
    int qt = blockIdx.x;
    int bh = blockIdx.y;
    int b = bh >> 4, h = bh & 15;
    const float scale = 0.08838834764831845f;

    for (int idx = tid; idx < 64 * 128; idx += 256) {
        int r = idx >> 7, c = idx & 127;
        Qs[idx] = q[(size_t)(b * Sn + qt * 64 + r) * Dn + h * HDn + c];
    }
    if (tid < 64) { m_s[tid] = -1e30f; l_s[tid] = 0.f; }
    float acc[8][4] = {};
    int tx = tid & 31, ty = tid >> 5;

    for (int kt = 0; kt <= qt; kt++) {
        __syncthreads();
        for (int idx = tid; idx < 64 * 128; idx += 256) {
            int r = idx >> 7, c = idx & 127;
            KVs[r * 129 + c] = k[(size_t)(b * Sn + kt * 64 + r) * Dn + h * HDn + c];
        }
        __syncthreads();
        for (int idx = tid; idx < 4096; idx += 256) {
            int r = idx >> 6, j = idx & 63;
            const float* qp = Qs + r * 128;
            const float* kp = KVs + j * 129;
            float s = 0.f;
#pragma unroll 16
            for (int kk = 0; kk < 128; kk++) s += qp[kk] * kp[kk];
            s *= scale;
            if (kt * 64 + j > qt * 64 + r) s = -1e30f;
            Ss[idx] = s;
        }
        __syncthreads();
        if (tid < 64) {
            int r = tid;
            float* sr = Ss + r * 64;
            float mo = m_s[r], tm = -1e30f;
            for (int j = 0; j < 64; j++) tm = fmaxf(tm, sr[j]);
            float nm = fmaxf(mo, tm);
            float a = expf(mo - nm);
            float sum = 0.f;
            for (int j = 0; j < 64; j++) { float p = expf(sr[j] - nm); sr[j] = p; sum += p; }
            l_s[r] = l_s[r] * a + sum;
            m_s[r] = nm;
            al_s[r] = a;
        }
        __syncthreads();
        for (int idx = tid; idx < 64 * 128; idx += 256) {
            int r = idx >> 7, c = idx & 127;
            KVs[r * 129 + c] = v[(size_t)(b * Sn + kt * 64 + r) * Dn + h * HDn + c];
        }
        __syncthreads();
#pragma unroll
        for (int i = 0; i < 8; i++) {
            int r = ty * 8 + i;
            float a = al_s[r];
            const float* pr = Ss + r * 64;
            float c0 = acc[i][0] * a, c1 = acc[i][1] * a;
            float c2 = acc[i][2] * a, c3 = acc[i][3] * a;
            for (int j = 0; j < 64; j++) {
                float p = pr[j];
                const float* vp = KVs + j * 129 + tx;
                c0 += p * vp[0];
                c1 += p * vp[32];
                c2 += p * vp[64];
                c3 += p * vp[96];
            }
            acc[i][0] = c0; acc[i][1] = c1; acc[i][2] = c2; acc[i][3] = c3;
        }
    }
#pragma unroll
    for (int i = 0; i < 8; i++) {
        int r = ty * 8 + i;
        float invl = 1.f / l_s[r];
        size_t base = (size_t)(b * Sn + qt * 64 + r) * Dn + h * HDn + tx;
        ctx[base]      = acc[i][0] * invl;
        ctx[base + 32] = acc[i][1] * invl;
        ctx[base + 64] = acc[i][2] * invl;
        ctx[base + 96] = acc[i][3] * invl;
    }
}

// ---------------- MoE routing ----------------
__global__ void k_zero() { if (threadIdx.x < En) g_cnt[threadIdx.x] = 0; }

__global__ void k_route(const float* __restrict__ h2, const float* __restrict__ gw) {
    int t = blockIdx.x;
    int lane = threadIdx.x & 31, wid = threadIdx.x >> 5;
    const float* hr = h2 + (size_t)t * Dn;
    const float* gr = gw + (size_t)wid * Dn;
    float s = 0.f;
    for (int i = lane; i < Dn; i += 32) s += hr[i] * gr[i];
    for (int o = 16; o; o >>= 1) s += __shfl_down_sync(0xffffffffu, s, o);
    __shared__ float lg[En];
    if (lane == 0) lg[wid] = s;
    __syncthreads();
    if (threadIdx.x == 0) {
        float mx = lg[0];
        for (int e = 1; e < En; e++) mx = fmaxf(mx, lg[e]);
        float p[En];
        for (int e = 0; e < En; e++) p[e] = expf(lg[e] - mx);
        int i1 = 0;
        for (int e = 1; e < En; e++) if (p[e] > p[i1]) i1 = e;
        int i2 = (i1 == 0) ? 1 : 0;
        for (int e = 0; e < En; e++) { if (e == i1) continue; if (p[e] > p[i2]) i2 = e; }
        float norm = p[i1] + p[i2];
        g_tok_e[t * 2]     = i1; g_tok_w[t * 2]     = p[i1] / norm;
        g_tok_e[t * 2 + 1] = i2; g_tok_w[t * 2 + 1] = p[i2] / norm;
        atomicAdd(&g_cnt[i1], 1);
        atomicAdd(&g_cnt[i2], 1);
    }
}

__global__ void k_scan() {
    if (threadIdx.x == 0) {
        int o = 0;
        for (int e = 0; e < En; e++) { g_off[e] = o; o += g_cnt[e]; g_run[e] = 0; }
    }
}

__global__ void k_place() {
    int t = blockIdx.x * 256 + threadIdx.x;
    if (t >= Tn) return;
    for (int kk = 0; kk < KKn; kk++) {
        int e = g_tok_e[t * 2 + kk];
        int pos = g_off[e] + atomicAdd(&g_run[e], 1);
        g_list_tok[pos] = t;
        g_tok_pos[t * 2 + kk] = pos;
    }
}

// ---------------- final: out = x1 + w0*ffn[p0] + w1*ffn[p1] ----------------
__global__ void k_final(float* __restrict__ out) {
    int t = blockIdx.x;
    int p0 = g_tok_pos[t * 2], p1 = g_tok_pos[t * 2 + 1];
    float w0 = g_tok_w[t * 2], w1 = g_tok_w[t * 2 + 1];
    const float4* x1 = (const float4*)(g_x1 + (size_t)t * Dn);
    const float4* f0 = (const float4*)(g_ffn + (size_t)p0 * Dn);
    const float4* f1 = (const float4*)(g_ffn + (size_t)p1 * Dn);
    float4* o = (float4*)(out + (size_t)t * Dn);
    for (int c = threadIdx.x; c < Dn / 4; c += 256) {
        float4 a = x1[c], b = f0[c], d = f1[c];
        a.x += w0 * b.x + w1 * d.x;
        a.y += w0 * b.y + w1 * d.y;
        a.z += w0 * b.z + w1 * d.z;
        a.w += w0 * b.w + w1 * d.w;
        o[c] = a;
    }
}

extern "C" void kernel_launch(void* const* d_in, const int* in_sizes, int n_in,
                              void* d_out, int out_size) {
    (void)in_sizes; (void)n_in; (void)out_size;
    const float* x   = (const float*)d_in[0];
    const float* ln1 = (const float*)d_in[3];
    const float* wq  = (const float*)d_in[4];
    const float* wk  = (const float*)d_in[5];
    const float* wv  = (const float*)d_in[6];
    const float* wo  = (const float*)d_in[7];
    const float* ln2 = (const float*)d_in[8];
    const float* gw  = (const float*)d_in[9];
    const float* w1  = (const float*)d_in[10];
    const float* w3  = (const float*)d_in[11];
    const float* w2  = (const float*)d_in[12];
    float* out = (float*)d_out;

    float *h1, *qb, *kb, *vb, *cb, *x1b, *h2b;
    cudaGetSymbolAddress((void**)&h1,  g_h1);
    cudaGetSymbolAddress((void**)&qb,  g_q);
    cudaGetSymbolAddress((void**)&kb,  g_k);
    cudaGetSymbolAddress((void**)&vb,  g_v);
    cudaGetSymbolAddress((void**)&cb,  g_ctx);
    cudaGetSymbolAddress((void**)&x1b, g_x1);
    cudaGetSymbolAddress((void**)&h2b, g_h2);

    const int smem_attn = ATTN_SMEM_FLOATS * 4;
    cudaFuncSetAttribute(k_attn, cudaFuncAttributeMaxDynamicSharedMemorySize, smem_attn);

    // 1. RMSNorm 1
    k_rmsnorm<<<Tn, 256>>>(x, ln1, h1);
    // 2. QKV projections (tf32 tensor cores)
    dim3 g1(Dn / 128, Tn / 128);
    k_mma_gemm<<<g1, 256>>>(h1, wq, nullptr, qb, Tn, Dn, Dn);
    k_mma_gemm<<<g1, 256>>>(h1, wk, nullptr, kb, Tn, Dn, Dn);
    k_mma_gemm<<<g1, 256>>>(h1, wv, nullptr, vb, Tn, Dn, Dn);
    // 3. RoPE
    k_rope<<<(Tn * Hn * 64) / 256, 256>>>(qb, kb);
    // 4. attention (fp32 flash)
    dim3 ga(Sn / 64, Bn * Hn);
    k_attn<<<ga, 256, smem_attn>>>(qb, kb, vb, cb);
    // 5. O projection + residual (tf32)
    k_mma_gemm<<<g1, 256>>>(cb, wo, x, x1b, Tn, Dn, Dn);
    // 6. RMSNorm 2
    k_rmsnorm<<<Tn, 256>>>(x1b, ln2, h2b);
    // 7. routing
    k_zero<<<1, 32>>>();
    k_route<<<Tn, 256>>>(h2b, gw);
    k_scan<<<1, 32>>>();
    k_place<<<Tn / 256, 256>>>();
    // 8. MoE expert GEMMs (tf32)
    dim3 gm1(Fn / 64, Tn / 128, En);
    k_mma_moe1<<<gm1, 256>>>(h2b, w1, w3);
    dim3 gm2(Dn / 128, Tn / 128, En);
    k_mma_moe2<<<gm2, 256>>>(w2);
    // 9. combine
    k_final<<<Tn, 256>>>(out);
}

// round 4
// speedup vs baseline: 2.7571x; 1.2411x over previous
#include <cuda_runtime.h>
#include <math.h>
#include <stdint.h>

#define Bn 2
#define Sn 2048
#define Dn 2048
#define Hn 16
#define HDn 128
#define Tn (Bn*Sn)
#define En 8
#define KKn 2
#define Fn 4096

__device__ float g_h1[Tn*Dn];
__device__ float g_q[Tn*Dn];
__device__ float g_k[Tn*Dn];
__device__ float g_v[Tn*Dn];
__device__ float g_ctx[Tn*Dn];
__device__ float g_x1[Tn*Dn];
__device__ float g_h2[Tn*Dn];
__device__ float g_act[(size_t)Tn*KKn*Fn];
__device__ float g_ffn[(size_t)Tn*KKn*Dn];
__device__ int   g_cnt[En];
__device__ int   g_off[En];
__device__ int   g_run[En];
__device__ int   g_tok_e[Tn*KKn];
__device__ float g_tok_w[Tn*KKn];
__device__ int   g_tok_pos[Tn*KKn];
__device__ int   g_list_tok[Tn*KKn];

__device__ __forceinline__ uint32_t f2tf(float f) {
    uint32_t u;
    asm("cvt.rna.tf32.f32 %0, %1;" : "=r"(u) : "f"(f));
    return u;
}
__device__ __forceinline__ void mma8(float* d, const uint32_t* a, const uint32_t* b) {
    asm volatile(
        "mma.sync.aligned.m16n8k8.row.col.f32.tf32.tf32.f32 "
        "{%0,%1,%2,%3}, {%4,%5,%6,%7}, {%8,%9}, {%0,%1,%2,%3};"
        : "+f"(d[0]), "+f"(d[1]), "+f"(d[2]), "+f"(d[3])
        : "r"(a[0]), "r"(a[1]), "r"(a[2]), "r"(a[3]), "r"(b[0]), "r"(b[1]));
}

// ---- swizzled [rows][16w] tiles: conflict-free STS.128 + LDS.32 ----
__device__ __forceinline__ void st_tile16(uint32_t* base, int r, int c4, float4 v) {
    int chunk = c4 ^ ((r >> 1) & 3);
    *(uint4*)(base + r * 16 + chunk * 4) =
        make_uint4(f2tf(v.x), f2tf(v.y), f2tf(v.z), f2tf(v.w));
}
__device__ __forceinline__ void ldA16(const uint32_t* base, int mf, int kk, int lane, uint32_t* av) {
    int g = lane >> 2, tig = lane & 3, sw = (g >> 1) & 3;
    int c0 = ((2 * kk) ^ sw) * 4 + tig, c1 = ((2 * kk + 1) ^ sw) * 4 + tig;
    const uint32_t* p = base + (mf * 16 + g) * 16;
    av[0] = p[c0]; av[1] = p[128 + c0]; av[2] = p[c1]; av[3] = p[128 + c1];
}
__device__ __forceinline__ void ldB16(const uint32_t* base, int nf, int kk, int lane, uint32_t* bv) {
    int g = lane >> 2, tig = lane & 3, sw = (g >> 1) & 3;
    const uint32_t* p = base + (nf * 8 + g) * 16;
    bv[0] = p[((2 * kk) ^ sw) * 4 + tig];
    bv[1] = p[((2 * kk + 1) ^ sw) * 4 + tig];
}

// ---------------- RMSNorm ----------------
__global__ void k_rmsnorm(const float* __restrict__ x, const float* __restrict__ w,
                          float* __restrict__ out) {
    int row = blockIdx.x;
    const float* xr = x + (size_t)row * Dn;
    float ss = 0.f;
    for (int i = threadIdx.x; i < Dn; i += 256) { float v = xr[i]; ss += v * v; }
    __shared__ float sh[256];
    sh[threadIdx.x] = ss;
    __syncthreads();
    for (int o = 128; o > 0; o >>= 1) {
        if (threadIdx.x < o) sh[threadIdx.x] += sh[threadIdx.x + o];
        __syncthreads();
    }
    float inv = rsqrtf(sh[0] / (float)Dn + 1e-6f);
    float* orow = out + (size_t)row * Dn;
    for (int i = threadIdx.x; i < Dn; i += 256) orow[i] = xr[i] * inv * w[i];
}

// ============ tf32 GEMM: C = A(MxK) @ B(NxK)^T (+R). 128x128x16 ============
__global__ __launch_bounds__(256) void k_mma_gemm(const float* __restrict__ A,
                                                  const float* __restrict__ B,
                                                  const float* __restrict__ R,
                                                  float* __restrict__ C,
                                                  int M, int N, int K) {
    __shared__ uint32_t As[2][128 * 16];
    __shared__ uint32_t Bs[2][128 * 16];
    int tid = threadIdx.x;
    int m0 = blockIdx.y * 128, n0 = blockIdx.x * 128;
    int lane = tid & 31, w = tid >> 5, wm = w >> 2, wn = w & 3;
    float acc[4][4][4] = {};
    float4 pa0, pa1, pb0, pb1;
#define GLDA(k0, i) (*(const float4*)(A + (size_t)(m0 + ((tid + 256*(i)) >> 2)) * K + (k0) + ((tid + 256*(i)) & 3) * 4))
#define GLDB(k0, i) (*(const float4*)(B + (size_t)(n0 + ((tid + 256*(i)) >> 2)) * K + (k0) + ((tid + 256*(i)) & 3) * 4))
    pa0 = GLDA(0, 0); pa1 = GLDA(0, 1);
    pb0 = GLDB(0, 0); pb1 = GLDB(0, 1);
    st_tile16(As[0], tid >> 2, tid & 3, pa0);
    st_tile16(As[0], (tid + 256) >> 2, tid & 3, pa1);
    st_tile16(Bs[0], tid >> 2, tid & 3, pb0);
    st_tile16(Bs[0], (tid + 256) >> 2, tid & 3, pb1);
    __syncthreads();
    int nit = K >> 4, buf = 0;
    for (int it = 0; it < nit; it++) {
        bool more = (it + 1) < nit;
        if (more) {
            int k0 = (it + 1) << 4;
            pa0 = GLDA(k0, 0); pa1 = GLDA(k0, 1);
            pb0 = GLDB(k0, 0); pb1 = GLDB(k0, 1);
        }
#pragma unroll
        for (int kk = 0; kk < 2; kk++) {
            uint32_t av[4][4], bv[4][2];
#pragma unroll
            for (int mi = 0; mi < 4; mi++) ldA16(As[buf], wm * 4 + mi, kk, lane, av[mi]);
#pragma unroll
            for (int ni = 0; ni < 4; ni++) ldB16(Bs[buf], wn * 4 + ni, kk, lane, bv[ni]);
#pragma unroll
            for (int mi = 0; mi < 4; mi++)
#pragma unroll
                for (int ni = 0; ni < 4; ni++) mma8(acc[mi][ni], av[mi], bv[ni]);
        }
        if (more) {
            st_tile16(As[buf ^ 1], tid >> 2, tid & 3, pa0);
            st_tile16(As[buf ^ 1], (tid + 256) >> 2, tid & 3, pa1);
            st_tile16(Bs[buf ^ 1], tid >> 2, tid & 3, pb0);
            st_tile16(Bs[buf ^ 1], (tid + 256) >> 2, tid & 3, pb1);
        }
        __syncthreads();
        buf ^= 1;
    }
#undef GLDA
#undef GLDB
    int g = lane >> 2, tig = lane & 3;
#pragma unroll
    for (int mi = 0; mi < 4; mi++) {
        int r1 = m0 + wm * 64 + mi * 16 + g, r2 = r1 + 8;
#pragma unroll
        for (int ni = 0; ni < 4; ni++) {
            int c = n0 + wn * 32 + ni * 8 + 2 * tig;
            float2 v1 = make_float2(acc[mi][ni][0], acc[mi][ni][1]);
            float2 v2 = make_float2(acc[mi][ni][2], acc[mi][ni][3]);
            if (R) {
                float2 q1 = *(const float2*)(R + (size_t)r1 * N + c);
                float2 q2 = *(const float2*)(R + (size_t)r2 * N + c);
                v1.x += q1.x; v1.y += q1.y; v2.x += q2.x; v2.y += q2.y;
            }
            *(float2*)(C + (size_t)r1 * N + c) = v1;
            *(float2*)(C + (size_t)r2 * N + c) = v2;
        }
    }
}

// ============ MoE GEMM1: act = silu(h@w1^T)*(h@w3^T). 128x64x16 ============
__global__ __launch_bounds__(256) void k_mma_moe1(const float* __restrict__ h2,
                                                   const float* __restrict__ w1,
                                                   const float* __restrict__ w3) {
    int e = blockIdx.z;
    int cnt = g_cnt[e];
    int m0 = blockIdx.y * 128;
    if (m0 >= cnt) return;
    int off = g_off[e];
    int n0 = blockIdx.x * 64;
    const float* B1 = w1 + (size_t)e * Fn * Dn;
    const float* B3 = w3 + (size_t)e * Fn * Dn;
    __shared__ uint32_t As[2][128 * 16];
    __shared__ uint32_t B1s[2][64 * 16];
    __shared__ uint32_t B3s[2][64 * 16];
    __shared__ int toks[128];
    int tid = threadIdx.x;
    if (tid < 128) toks[tid] = (m0 + tid < cnt) ? g_list_tok[off + m0 + tid] : g_list_tok[off];
    __syncthreads();
    int lane = tid & 31, w = tid >> 5, wm = w >> 2, wn = w & 3;
    float aU[4][2][4] = {}, aG[4][2][4] = {};
    float4 pa0, pa1, pb1, pb3;
#define GLDA(k0, i) (*(const float4*)(h2 + (size_t)toks[(tid + 256*(i)) >> 2] * Dn + (k0) + ((tid + 256*(i)) & 3) * 4))
#define GLD1(k0) (*(const float4*)(B1 + (size_t)(n0 + (tid >> 2)) * Dn + (k0) + (tid & 3) * 4))
#define GLD3(k0) (*(const float4*)(B3 + (size_t)(n0 + (tid >> 2)) * Dn + (k0) + (tid & 3) * 4))
    pa0 = GLDA(0, 0); pa1 = GLDA(0, 1); pb1 = GLD1(0); pb3 = GLD3(0);
    st_tile16(As[0], tid >> 2, tid & 3, pa0);
    st_tile16(As[0], (tid + 256) >> 2, tid & 3, pa1);
    st_tile16(B1s[0], tid >> 2, tid & 3, pb1);
    st_tile16(B3s[0], tid >> 2, tid & 3, pb3);
    __syncthreads();
    int nit = Dn >> 4, buf = 0;
    for (int it = 0; it < nit; it++) {
        bool more = (it + 1) < nit;
        if (more) {
            int k0 = (it + 1) << 4;
            pa0 = GLDA(k0, 0); pa1 = GLDA(k0, 1);
            pb1 = GLD1(k0); pb3 = GLD3(k0);
        }
#pragma unroll
        for (int kk = 0; kk < 2; kk++) {
            uint32_t av[4][4], b1v[2][2], b3v[2][2];
#pragma unroll
            for (int mi = 0; mi < 4; mi++) ldA16(As[buf], wm * 4 + mi, kk, lane, av[mi]);
#pragma unroll
            for (int ni = 0; ni < 2; ni++) {
                ldB16(B1s[buf], wn * 2 + ni, kk, lane, b1v[ni]);
                ldB16(B3s[buf], wn * 2 + ni, kk, lane, b3v[ni]);
            }
#pragma unroll
            for (int mi = 0; mi < 4; mi++)
#pragma unroll
                for (int ni = 0; ni < 2; ni++) {
                    mma8(aU[mi][ni], av[mi], b1v[ni]);
                    mma8(aG[mi][ni], av[mi], b3v[ni]);
                }
        }
        if (more) {
            st_tile16(As[buf ^ 1], tid >> 2, tid & 3, pa0);
            st_tile16(As[buf ^ 1], (tid + 256) >> 2, tid & 3, pa1);
            st_tile16(B1s[buf ^ 1], tid >> 2, tid & 3, pb1);
            st_tile16(B3s[buf ^ 1], tid >> 2, tid & 3, pb3);
        }
        __syncthreads();
        buf ^= 1;
    }
#undef GLDA
#undef GLD1
#undef GLD3
    int g = lane >> 2, tig = lane & 3;
#pragma unroll
    for (int mi = 0; mi < 4; mi++)
#pragma unroll
        for (int half = 0; half < 2; half++) {
            int r = m0 + wm * 64 + mi * 16 + g + half * 8;
            if (r >= cnt) continue;
            float* dst = g_act + (size_t)(off + r) * Fn;
#pragma unroll
            for (int ni = 0; ni < 2; ni++) {
                int c = n0 + wn * 16 + ni * 8 + 2 * tig;
                float u0 = aU[mi][ni][half * 2], g0 = aG[mi][ni][half * 2];
                float u1 = aU[mi][ni][half * 2 + 1], g1 = aG[mi][ni][half * 2 + 1];
                *(float2*)(dst + c) = make_float2(u0 / (1.f + expf(-u0)) * g0,
                                                  u1 / (1.f + expf(-u1)) * g1);
            }
        }
}

// ============ MoE GEMM2: ffn = act @ w2^T. 128x128x16 ============
__global__ __launch_bounds__(256) void k_mma_moe2(const float* __restrict__ w2) {
    int e = blockIdx.z;
    int cnt = g_cnt[e];
    int m0 = blockIdx.y * 128;
    if (m0 >= cnt) return;
    int off = g_off[e];
    int n0 = blockIdx.x * 128;
    const float* A = g_act + (size_t)off * Fn;
    const float* B = w2 + (size_t)e * Dn * Fn;
    __shared__ uint32_t As[2][128 * 16];
    __shared__ uint32_t Bs[2][128 * 16];
    int tid = threadIdx.x;
    int lane = tid & 31, w = tid >> 5, wm = w >> 2, wn = w & 3;
    float acc[4][4][4] = {};
    float4 pa0, pa1, pb0, pb1;
#define ARow(i) min(m0 + ((tid + 256*(i)) >> 2), cnt - 1)
#define GLDA(k0, i) (*(const float4*)(A + (size_t)ARow(i) * Fn + (k0) + ((tid + 256*(i)) & 3) * 4))
#define GLDB(k0, i) (*(const float4*)(B + (size_t)(n0 + ((tid + 256*(i)) >> 2)) * Fn + (k0) + ((tid + 256*(i)) & 3) * 4))
    pa0 = GLDA(0, 0); pa1 = GLDA(0, 1);
    pb0 = GLDB(0, 0); pb1 = GLDB(0, 1);
    st_tile16(As[0], tid >> 2, tid & 3, pa0);
    st_tile16(As[0], (tid + 256) >> 2, tid & 3, pa1);
    st_tile16(Bs[0], tid >> 2, tid & 3, pb0);
    st_tile16(Bs[0], (tid + 256) >> 2, tid & 3, pb1);
    __syncthreads();
    int nit = Fn >> 4, buf = 0;
    for (int it = 0; it < nit; it++) {
        bool more = (it + 1) < nit;
        if (more) {
            int k0 = (it + 1) << 4;
            pa0 = GLDA(k0, 0); pa1 = GLDA(k0, 1);
            pb0 = GLDB(k0, 0); pb1 = GLDB(k0, 1);
        }
#pragma unroll
        for (int kk = 0; kk < 2; kk++) {
            uint32_t av[4][4], bv[4][2];
#pragma unroll
            for (int mi = 0; mi < 4; mi++) ldA16(As[buf], wm * 4 + mi, kk, lane, av[mi]);
#pragma unroll
            for (int ni = 0; ni < 4; ni++) ldB16(Bs[buf], wn * 4 + ni, kk, lane, bv[ni]);
#pragma unroll
            for (int mi = 0; mi < 4; mi++)
#pragma unroll
                for (int ni = 0; ni < 4; ni++) mma8(acc[mi][ni], av[mi], bv[ni]);
        }
        if (more) {
            st_tile16(As[buf ^ 1], tid >> 2, tid & 3, pa0);
            st_tile16(As[buf ^ 1], (tid + 256) >> 2, tid & 3, pa1);
            st_tile16(Bs[buf ^ 1], tid >> 2, tid & 3, pb0);
            st_tile16(Bs[buf ^ 1], (tid + 256) >> 2, tid & 3, pb1);
        }
        __syncthreads();
        buf ^= 1;
    }
#undef ARow
#undef GLDA
#undef GLDB
    int g = lane >> 2, tig = lane & 3;
#pragma unroll
    for (int mi = 0; mi < 4; mi++) {
        int r1 = m0 + wm * 64 + mi * 16 + g, r2 = r1 + 8;
#pragma unroll
        for (int ni = 0; ni < 4; ni++) {
            int c = n0 + wn * 32 + ni * 8 + 2 * tig;
            if (r1 < cnt)
                *(float2*)(g_ffn + (size_t)(off + r1) * Dn + c) = make_float2(acc[mi][ni][0], acc[mi][ni][1]);
            if (r2 < cnt)
                *(float2*)(g_ffn + (size_t)(off + r2) * Dn + c) = make_float2(acc[mi][ni][2], acc[mi][ni][3]);
        }
    }
}

// ---------------- RoPE ----------------
__global__ void k_rope(float* __restrict__ q, float* __restrict__ k) {
    int gid = blockIdx.x * 256 + threadIdx.x;
    if (gid >= Tn * Hn * 64) return;
    int i = gid & 63;
    int h = (gid >> 6) & (Hn - 1);
    int t = gid >> 10;
    int s = t & (Sn - 1);
    float inv = powf(10000.0f, -(float)i / 64.0f);
    float ang = (float)s * inv, sn, c;
    sincosf(ang, &sn, &c);
    size_t base = (size_t)t * Dn + h * HDn;
    float q1 = q[base + i], q2 = q[base + i + 64];
    q[base + i]      = q1 * c - q2 * sn;
    q[base + i + 64] = q2 * c + q1 * sn;
    float k1 = k[base + i], k2 = k[base + i + 64];
    k[base + i]      = k1 * c - k2 * sn;
    k[base + i + 64] = k2 * c + k1 * sn;
}

// ============ tf32 flash attention: 128 q-rows x 64 keys/iter ============
// strides: Q,K pad 132; V pad 136; P pad 68 (all audited conflict-free)
#define ATT_WORDS (128*132 + 64*132 + 64*136 + 128*68)
__global__ __launch_bounds__(256) void k_attn_mma(const float* __restrict__ q,
                                                  const float* __restrict__ k,
                                                  const float* __restrict__ v,
                                                  float* __restrict__ ctx) {
    extern __shared__ uint32_t sm[];
    uint32_t* Qs = sm;                 // 128 x 132
    uint32_t* Ks = Qs + 128 * 132;     // 64 x 132
    uint32_t* Vs = Ks + 64 * 132;      // 64 x 136
    uint32_t* Ps = Vs + 64 * 136;      // 128 x 68
    int tid = threadIdx.x, lane = tid & 31, w = tid >> 5;
    int qt = blockIdx.x, bh = blockIdx.y, b = bh >> 4, h = bh & 15;
    int g = lane >> 2, tig = lane & 3;
    const float scale = 0.08838834764831845f;

    for (int i = 0; i < 16; i++) {
        int idx = tid + 256 * i;
        int r = idx >> 5, c4 = idx & 31;
        float4 val = *(const float4*)(q + (size_t)(b * Sn + qt * 128 + r) * Dn + h * HDn + c4 * 4);
        *(uint4*)(Qs + r * 132 + c4 * 4) =
            make_uint4(f2tf(val.x), f2tf(val.y), f2tf(val.z), f2tf(val.w));
    }
    float o_acc[16][4] = {};
    float mrow0 = -1e30f, mrow1 = -1e30f, lrow0 = 0.f, lrow1 = 0.f;
    int wbase = qt * 128 + w * 16;
    int row_hi = wbase + 15;
    int r0g = wbase + g, r1g = r0g + 8;

    int nkt = 2 * qt + 2;
    for (int kt = 0; kt < nkt; kt++) {
        __syncthreads();
        for (int i = 0; i < 8; i++) {
            int idx = tid + 256 * i;
            int r = idx >> 5, c4 = idx & 31;
            size_t gofs = (size_t)(b * Sn + kt * 64 + r) * Dn + h * HDn + c4 * 4;
            float4 kv = *(const float4*)(k + gofs);
            float4 vv = *(const float4*)(v + gofs);
            *(uint4*)(Ks + r * 132 + c4 * 4) =
                make_uint4(f2tf(kv.x), f2tf(kv.y), f2tf(kv.z), f2tf(kv.w));
            *(uint4*)(Vs + r * 136 + c4 * 4) =
                make_uint4(f2tf(vv.x), f2tf(vv.y), f2tf(vv.z), f2tf(vv.w));
        }
        __syncthreads();
        if (kt * 64 > row_hi) continue;

        // S = Q K^T
        float sacc[8][4] = {};
#pragma unroll
        for (int kk = 0; kk < 16; kk++) {
            uint32_t av[4];
            const uint32_t* qp = Qs + (w * 16 + g) * 132 + kk * 8 + tig;
            av[0] = qp[0]; av[1] = qp[8 * 132]; av[2] = qp[4]; av[3] = qp[8 * 132 + 4];
#pragma unroll
            for (int nf = 0; nf < 8; nf++) {
                uint32_t bv[2];
                const uint32_t* kp = Ks + (nf * 8 + g) * 132 + kk * 8 + tig;
                bv[0] = kp[0]; bv[1] = kp[4];
                mma8(sacc[nf], av, bv);
            }
        }
        // mask + online softmax (rows r0g, r1g; quad-wide)
        bool need_mask = (kt * 64 + 63) > wbase;
        float mx0 = -1e30f, mx1 = -1e30f;
#pragma unroll
        for (int nf = 0; nf < 8; nf++) {
            int c0 = kt * 64 + nf * 8 + 2 * tig;
#pragma unroll
            for (int j = 0; j < 4; j++) {
                float s = sacc[nf][j] * scale;
                if (need_mask) {
                    int col = c0 + (j & 1);
                    int rg = (j < 2) ? r0g : r1g;
                    if (col > rg) s = -1e30f;
                }
                sacc[nf][j] = s;
                if (j < 2) mx0 = fmaxf(mx0, s); else mx1 = fmaxf(mx1, s);
            }
        }
        mx0 = fmaxf(mx0, __shfl_xor_sync(0xffffffffu, mx0, 1));
        mx0 = fmaxf(mx0, __shfl_xor_sync(0xffffffffu, mx0, 2));
        mx1 = fmaxf(mx1, __shfl_xor_sync(0xffffffffu, mx1, 1));
        mx1 = fmaxf(mx1, __shfl_xor_sync(0xffffffffu, mx1, 2));
        float mn0 = fmaxf(mrow0, mx0), mn1 = fmaxf(mrow1, mx1);
        float a0 = expf(mrow0 - mn0), a1 = expf(mrow1 - mn1);
        mrow0 = mn0; mrow1 = mn1;
        float sum0 = 0.f, sum1 = 0.f;
#pragma unroll
        for (int nf = 0; nf < 8; nf++) {
            float p0 = expf(sacc[nf][0] - mn0), p1 = expf(sacc[nf][1] - mn0);
            float p2 = expf(sacc[nf][2] - mn1), p3 = expf(sacc[nf][3] - mn1);
            sacc[nf][0] = p0; sacc[nf][1] = p1; sacc[nf][2] = p2; sacc[nf][3] = p3;
            sum0 += p0 + p1; sum1 += p2 + p3;
        }
        sum0 += __shfl_xor_sync(0xffffffffu, sum0, 1);
        sum0 += __shfl_xor_sync(0xffffffffu, sum0, 2);
        sum1 += __shfl_xor_sync(0xffffffffu, sum1, 1);
        sum1 += __shfl_xor_sync(0xffffffffu, sum1, 2);
        lrow0 = lrow0 * a0 + sum0;
        lrow1 = lrow1 * a1 + sum1;
#pragma unroll
        for (int nf = 0; nf < 16; nf++) {
            o_acc[nf][0] *= a0; o_acc[nf][1] *= a0;
            o_acc[nf][2] *= a1; o_acc[nf][3] *= a1;
        }
        // store P (warp-local region)
        int pr0 = w * 16 + g;
#pragma unroll
        for (int nf = 0; nf < 8; nf++) {
            int cb = nf * 8 + 2 * tig;
            Ps[pr0 * 68 + cb]           = f2tf(sacc[nf][0]);
            Ps[pr0 * 68 + cb + 1]       = f2tf(sacc[nf][1]);
            Ps[(pr0 + 8) * 68 + cb]     = f2tf(sacc[nf][2]);
            Ps[(pr0 + 8) * 68 + cb + 1] = f2tf(sacc[nf][3]);
        }
        __syncwarp();
        // O += P V
#pragma unroll
        for (int kk = 0; kk < 8; kk++) {
            uint32_t av[4];
            const uint32_t* pp = Ps + (w * 16 + g) * 68 + kk * 8 + tig;
            av[0] = pp[0]; av[1] = pp[8 * 68]; av[2] = pp[4]; av[3] = pp[8 * 68 + 4];
#pragma unroll
            for (int nf = 0; nf < 16; nf++) {
                uint32_t bv[2];
                const uint32_t* vp = Vs + (kk * 8 + tig) * 136 + nf * 8 + g;
                bv[0] = vp[0]; bv[1] = vp[4 * 136];
                mma8(o_acc[nf], av, bv);
            }
        }
        __syncwarp();
    }
    float inv0 = 1.f / lrow0, inv1 = 1.f / lrow1;
    size_t ro0 = (size_t)(b * Sn + r0g) * Dn, ro1 = (size_t)(b * Sn + r1g) * Dn;
#pragma unroll
    for (int nf = 0; nf < 16; nf++) {
        int c = h * HDn + nf * 8 + 2 * tig;
        *(float2*)(ctx + ro0 + c) = make_float2(o_acc[nf][0] * inv0, o_acc[nf][1] * inv0);
        *(float2*)(ctx + ro1 + c) = make_float2(o_acc[nf][2] * inv1, o_acc[nf][3] * inv1);
    }
}

// ---------------- MoE routing ----------------
__global__ void k_zero() { if (threadIdx.x < En) g_cnt[threadIdx.x] = 0; }

__global__ void k_route(const float* __restrict__ h2, const float* __restrict__ gw) {
    int t = blockIdx.x;
    int lane = threadIdx.x & 31, wid = threadIdx.x >> 5;
    const float* hr = h2 + (size_t)t * Dn;
    const float* gr = gw + (size_t)wid * Dn;
    float s = 0.f;
    for (int i = lane; i < Dn; i += 32) s += hr[i] * gr[i];
    for (int o = 16; o; o >>= 1) s += __shfl_down_sync(0xffffffffu, s, o);
    __shared__ float lg[En];
    if (lane == 0) lg[wid] = s;
    __syncthreads();
    if (threadIdx.x == 0) {
        float mx = lg[0];
        for (int e = 1; e < En; e++) mx = fmaxf(mx, lg[e]);
        float p[En];
        for (int e = 0; e < En; e++) p[e] = expf(lg[e] - mx);
        int i1 = 0;
        for (int e = 1; e < En; e++) if (p[e] > p[i1]) i1 = e;
        int i2 = (i1 == 0) ? 1 : 0;
        for (int e = 0; e < En; e++) { if (e == i1) continue; if (p[e] > p[i2]) i2 = e; }
        float norm = p[i1] + p[i2];
        g_tok_e[t * 2]     = i1; g_tok_w[t * 2]     = p[i1] / norm;
        g_tok_e[t * 2 + 1] = i2; g_tok_w[t * 2 + 1] = p[i2] / norm;
        atomicAdd(&g_cnt[i1], 1);
        atomicAdd(&g_cnt[i2], 1);
    }
}

__global__ void k_scan() {
    if (threadIdx.x == 0) {
        int o = 0;
        for (int e = 0; e < En; e++) { g_off[e] = o; o += g_cnt[e]; g_run[e] = 0; }
    }
}

__global__ void k_place() {
    int t = blockIdx.x * 256 + threadIdx.x;
    if (t >= Tn) return;
    for (int kk = 0; kk < KKn; kk++) {
        int e = g_tok_e[t * 2 + kk];
        int pos = g_off[e] + atomicAdd(&g_run[e], 1);
        g_list_tok[pos] = t;
        g_tok_pos[t * 2 + kk] = pos;
    }
}

// ---------------- final combine ----------------
__global__ void k_final(float* __restrict__ out) {
    int t = blockIdx.x;
    int p0 = g_tok_pos[t * 2], p1 = g_tok_pos[t * 2 + 1];
    float w0 = g_tok_w[t * 2], w1 = g_tok_w[t * 2 + 1];
    const float4* x1 = (const float4*)(g_x1 + (size_t)t * Dn);
    const float4* f0 = (const float4*)(g_ffn + (size_t)p0 * Dn);
    const float4* f1 = (const float4*)(g_ffn + (size_t)p1 * Dn);
    float4* o = (float4*)(out + (size_t)t * Dn);
    for (int c = threadIdx.x; c < Dn / 4; c += 256) {
        float4 a = x1[c], b = f0[c], d = f1[c];
        a.x += w0 * b.x + w1 * d.x;
        a.y += w0 * b.y + w1 * d.y;
        a.z += w0 * b.z + w1 * d.z;
        a.w += w0 * b.w + w1 * d.w;
        o[c] = a;
    }
}

extern "C" void kernel_launch(void* const* d_in, const int* in_sizes, int n_in,
                              void* d_out, int out_size) {
    (void)in_sizes; (void)n_in; (void)out_size;
    const float* x   = (const float*)d_in[0];
    const float* ln1 = (const float*)d_in[3];
    const float* wq  = (const float*)d_in[4];
    const float* wk  = (const float*)d_in[5];
    const float* wv  = (const float*)d_in[6];
    const float* wo  = (const float*)d_in[7];
    const float* ln2 = (const float*)d_in[8];
    const float* gw  = (const float*)d_in[9];
    const float* w1  = (const float*)d_in[10];
    const float* w3  = (const float*)d_in[11];
    const float* w2  = (const float*)d_in[12];
    float* out = (float*)d_out;

    float *h1, *qb, *kb, *vb, *cb, *x1b, *h2b;
    cudaGetSymbolAddress((void**)&h1,  g_h1);
    cudaGetSymbolAddress((void**)&qb,  g_q);
    cudaGetSymbolAddress((void**)&kb,  g_k);
    cudaGetSymbolAddress((void**)&vb,  g_v);
    cudaGetSymbolAddress((void**)&cb,  g_ctx);
    cudaGetSymbolAddress((void**)&x1b, g_x1);
    cudaGetSymbolAddress((void**)&h2b, g_h2);

    const int smem_attn = ATT_WORDS * 4;
    cudaFuncSetAttribute(k_attn_mma, cudaFuncAttributeMaxDynamicSharedMemorySize, smem_attn);

    k_rmsnorm<<<Tn, 256>>>(x, ln1, h1);
    dim3 g1(Dn / 128, Tn / 128);
    k_mma_gemm<<<g1, 256>>>(h1, wq, nullptr, qb, Tn, Dn, Dn);
    k_mma_gemm<<<g1, 256>>>(h1, wk, nullptr, kb, Tn, Dn, Dn);
    k_mma_gemm<<<g1, 256>>>(h1, wv, nullptr, vb, Tn, Dn, Dn);
    k_rope<<<(Tn * Hn * 64) / 256, 256>>>(qb, kb);
    dim3 ga(Sn / 128, Bn * Hn);
    k_attn_mma<<<ga, 256, smem_attn>>>(qb, kb, vb, cb);
    k_mma_gemm<<<g1, 256>>>(cb, wo, x, x1b, Tn, Dn, Dn);
    k_rmsnorm<<<Tn, 256>>>(x1b, ln2, h2b);
    k_zero<<<1, 32>>>();
    k_route<<<Tn, 256>>>(h2b, gw);
    k_scan<<<1, 32>>>();
    k_place<<<Tn / 256, 256>>>();
    dim3 gm1(Fn / 64, Tn / 128, En);
    k_mma_moe1<<<gm1, 256>>>(h2b, w1, w3);
    dim3 gm2(Dn / 128, Tn / 128, En);
    k_mma_moe2<<<gm2, 256>>>(w2);
    k_final<<<Tn, 256>>>(out);
}

// round 6
// speedup vs baseline: 4.7618x; 1.7271x over previous
#include <cuda_runtime.h>
#include <cuda_fp16.h>
#include <math.h>
#include <stdint.h>

#define Bn 2
#define Sn 2048
#define Dn 2048
#define Hn 16
#define HDn 128
#define Tn (Bn*Sn)
#define En 8
#define KKn 2
#define Fn 4096

__device__ float g_h1[Tn*Dn];
__device__ float g_q[Tn*Dn];
__device__ float g_k[Tn*Dn];
__device__ float g_v[Tn*Dn];
__device__ float g_ctx[Tn*Dn];
__device__ float g_x1[Tn*Dn];
__device__ float g_h2[Tn*Dn];
__device__ float g_act[(size_t)Tn*KKn*Fn];
__device__ float g_ffn[(size_t)Tn*KKn*Dn];
__device__ int   g_cnt[En];
__device__ int   g_off[En];
__device__ int   g_run[En];
__device__ int   g_tok_e[Tn*KKn];
__device__ float g_tok_w[Tn*KKn];
__device__ int   g_tok_pos[Tn*KKn];
__device__ int   g_list_tok[Tn*KKn];

__device__ __forceinline__ uint32_t f2tf(float f) {
    uint32_t u;
    asm("cvt.rna.tf32.f32 %0, %1;" : "=r"(u) : "f"(f));
    return u;
}
__device__ __forceinline__ uint32_t f2h2(float a, float b) {
    __half2 h = __floats2half2_rn(a, b);
    return *(uint32_t*)&h;
}
// fp16 m16n8k16, fp32 accumulate
__device__ __forceinline__ void mma16(float* d, const uint32_t* a, const uint32_t* b) {
    asm volatile(
        "mma.sync.aligned.m16n8k16.row.col.f32.f16.f16.f32 "
        "{%0,%1,%2,%3}, {%4,%5,%6,%7}, {%8,%9}, {%0,%1,%2,%3};"
        : "+f"(d[0]), "+f"(d[1]), "+f"(d[2]), "+f"(d[3])
        : "r"(a[0]), "r"(a[1]), "r"(a[2]), "r"(a[3]), "r"(b[0]), "r"(b[1]));
}
// tf32 m16n8k8 (attention)
__device__ __forceinline__ void mma8(float* d, const uint32_t* a, const uint32_t* b) {
    asm volatile(
        "mma.sync.aligned.m16n8k8.row.col.f32.tf32.tf32.f32 "
        "{%0,%1,%2,%3}, {%4,%5,%6,%7}, {%8,%9}, {%0,%1,%2,%3};"
        : "+f"(d[0]), "+f"(d[1]), "+f"(d[2]), "+f"(d[3])
        : "r"(a[0]), "r"(a[1]), "r"(a[2]), "r"(a[3]), "r"(b[0]), "r"(b[1]));
}

// ---------------- RMSNorm ----------------
__global__ void k_rmsnorm(const float* __restrict__ x, const float* __restrict__ w,
                          float* __restrict__ out) {
    int row = blockIdx.x;
    const float* xr = x + (size_t)row * Dn;
    float ss = 0.f;
    for (int i = threadIdx.x; i < Dn; i += 256) { float v = xr[i]; ss += v * v; }
    __shared__ float sh[256];
    sh[threadIdx.x] = ss;
    __syncthreads();
    for (int o = 128; o > 0; o >>= 1) {
        if (threadIdx.x < o) sh[threadIdx.x] += sh[threadIdx.x + o];
        __syncthreads();
    }
    float inv = rsqrtf(sh[0] / (float)Dn + 1e-6f);
    float* orow = out + (size_t)row * Dn;
    for (int i = threadIdx.x; i < Dn; i += 256) orow[i] = xr[i] * inv * w[i];
}

// ============================================================================
// fp16 tensor GEMM: C = A(MxK) @ B(NxK)^T (+R). CTA 128x128x32, 8 warps 64x32.
// smem rows padded to 20 words (40 fp16): frag LDS conflict-free.
// ============================================================================
// load 16 fp32 of row lr, k-half lh (16 cols) into 8 half2 words
#define LOADROW(dst, ptr) { \
    const float4* p4_ = (const float4*)(ptr); \
    float4 v0_ = p4_[0], v1_ = p4_[1], v2_ = p4_[2], v3_ = p4_[3]; \
    dst[0] = make_uint2(f2h2(v0_.x, v0_.y), f2h2(v0_.z, v0_.w)); \
    dst[1] = make_uint2(f2h2(v1_.x, v1_.y), f2h2(v1_.z, v1_.w)); \
    dst[2] = make_uint2(f2h2(v2_.x, v2_.y), f2h2(v2_.z, v2_.w)); \
    dst[3] = make_uint2(f2h2(v3_.x, v3_.y), f2h2(v3_.z, v3_.w)); }
#define STROW(base, lr, lh, src) { \
    uint32_t* s_ = (base) + (lr) * 20 + (lh) * 8; \
    *(uint4*)s_       = make_uint4(src[0].x, src[0].y, src[1].x, src[1].y); \
    *(uint4*)(s_ + 4) = make_uint4(src[2].x, src[2].y, src[3].x, src[3].y); }

__global__ __launch_bounds__(256) void k_h_gemm(const float* __restrict__ A,
                                                const float* __restrict__ B,
                                                const float* __restrict__ R,
                                                float* __restrict__ C,
                                                int M, int ldC, int K) {
    __shared__ uint32_t As[2][128 * 20];
    __shared__ uint32_t Bs[2][128 * 20];
    int tid = threadIdx.x, lane = tid & 31, w = tid >> 5;
    int wm = w >> 2, wn = w & 3;
    int g = lane >> 2, t = lane & 3;
    int m0 = blockIdx.y * 128, n0 = blockIdx.x * 128;
    int lr = tid >> 1, lh = tid & 1;
    float acc[4][4][4] = {};
    uint2 pa[4], pb[4];

    const float* Ab = A + (size_t)(m0 + lr) * K + lh * 16;
    const float* Bb = B + (size_t)(n0 + lr) * K + lh * 16;
    LOADROW(pa, Ab); LOADROW(pb, Bb);
    STROW(As[0], lr, lh, pa); STROW(Bs[0], lr, lh, pb);
    __syncthreads();

    int nit = K >> 5, buf = 0;
    for (int it = 0; it < nit; it++) {
        bool more = (it + 1) < nit;
        if (more) {
            LOADROW(pa, Ab + (it + 1) * 32);
            LOADROW(pb, Bb + (it + 1) * 32);
        }
#pragma unroll
        for (int kk = 0; kk < 2; kk++) {
            uint32_t av[4][4], bv[4][2];
#pragma unroll
            for (int mf = 0; mf < 4; mf++) {
                const uint32_t* p = &As[buf][(wm * 64 + mf * 16 + g) * 20 + kk * 8 + t];
                av[mf][0] = p[0]; av[mf][1] = p[160]; av[mf][2] = p[4]; av[mf][3] = p[164];
            }
#pragma unroll
            for (int nf = 0; nf < 4; nf++) {
                const uint32_t* p = &Bs[buf][(wn * 32 + nf * 8 + g) * 20 + kk * 8 + t];
                bv[nf][0] = p[0]; bv[nf][1] = p[4];
            }
#pragma unroll
            for (int mf = 0; mf < 4; mf++)
#pragma unroll
                for (int nf = 0; nf < 4; nf++) mma16(acc[mf][nf], av[mf], bv[nf]);
        }
        if (more) {
            STROW(As[buf ^ 1], lr, lh, pa);
            STROW(Bs[buf ^ 1], lr, lh, pb);
        }
        __syncthreads();
        buf ^= 1;
    }
#pragma unroll
    for (int mf = 0; mf < 4; mf++) {
        int r1 = m0 + wm * 64 + mf * 16 + g, r2 = r1 + 8;
#pragma unroll
        for (int nf = 0; nf < 4; nf++) {
            int c = n0 + wn * 32 + nf * 8 + 2 * t;
            float2 v1 = make_float2(acc[mf][nf][0], acc[mf][nf][1]);
            float2 v2 = make_float2(acc[mf][nf][2], acc[mf][nf][3]);
            if (R) {
                float2 q1 = *(const float2*)(R + (size_t)r1 * ldC + c);
                float2 q2 = *(const float2*)(R + (size_t)r2 * ldC + c);
                v1.x += q1.x; v1.y += q1.y; v2.x += q2.x; v2.y += q2.y;
            }
            *(float2*)(C + (size_t)r1 * ldC + c) = v1;
            *(float2*)(C + (size_t)r2 * ldC + c) = v2;
        }
    }
}

// ============================================================================
// fp16 MoE GEMM1: act = silu(h@w1^T)*(h@w3^T). CTA 128x64x32, dual B.
// ============================================================================
__global__ __launch_bounds__(256) void k_h_moe1(const float* __restrict__ h2,
                                                const float* __restrict__ w1,
                                                const float* __restrict__ w3) {
    int e = blockIdx.z;
    int cnt = g_cnt[e];
    int m0 = blockIdx.y * 128;
    if (m0 >= cnt) return;
    int off = g_off[e];
    int n0 = blockIdx.x * 64;
    const float* B1 = w1 + (size_t)e * Fn * Dn;
    const float* B3 = w3 + (size_t)e * Fn * Dn;
    __shared__ uint32_t As[2][128 * 20];
    __shared__ uint32_t B1s[2][64 * 20];
    __shared__ uint32_t B3s[2][64 * 20];
    __shared__ int toks[128];
    int tid = threadIdx.x, lane = tid & 31, w = tid >> 5;
    int wm = w >> 2, wn = w & 3;
    int g = lane >> 2, t = lane & 3;
    if (tid < 128) toks[tid] = (m0 + tid < cnt) ? g_list_tok[off + m0 + tid] : g_list_tok[off];
    __syncthreads();

    int lr = tid >> 1, lh = tid & 1;          // A loader: rows 0..127
    int br = (tid & 127) >> 1, bh = tid & 1;  // B loader: rows 0..63, tid<128 -> B1 else B3
    bool isB1 = tid < 128;
    float aU[4][2][4] = {}, aG[4][2][4] = {};
    uint2 pa[4], pb[4];

    const float* Ab = h2 + (size_t)toks[lr] * Dn + lh * 16;
    const float* Bb = (isB1 ? B1 : B3) + (size_t)(n0 + br) * Dn + bh * 16;
    uint32_t* Bdst0 = isB1 ? B1s[0] : B3s[0];
    LOADROW(pa, Ab); LOADROW(pb, Bb);
    STROW(As[0], lr, lh, pa); STROW(Bdst0, br, bh, pb);
    __syncthreads();

    int nit = Dn >> 5, buf = 0;
    for (int it = 0; it < nit; it++) {
        bool more = (it + 1) < nit;
        if (more) {
            LOADROW(pa, Ab + (it + 1) * 32);
            LOADROW(pb, Bb + (it + 1) * 32);
        }
#pragma unroll
        for (int kk = 0; kk < 2; kk++) {
            uint32_t av[4][4], b1v[2][2], b3v[2][2];
#pragma unroll
            for (int mf = 0; mf < 4; mf++) {
                const uint32_t* p = &As[buf][(wm * 64 + mf * 16 + g) * 20 + kk * 8 + t];
                av[mf][0] = p[0]; av[mf][1] = p[160]; av[mf][2] = p[4]; av[mf][3] = p[164];
            }
#pragma unroll
            for (int nf = 0; nf < 2; nf++) {
                const uint32_t* p1 = &B1s[buf][(wn * 16 + nf * 8 + g) * 20 + kk * 8 + t];
                b1v[nf][0] = p1[0]; b1v[nf][1] = p1[4];
                const uint32_t* p3 = &B3s[buf][(wn * 16 + nf * 8 + g) * 20 + kk * 8 + t];
                b3v[nf][0] = p3[0]; b3v[nf][1] = p3[4];
            }
#pragma unroll
            for (int mf = 0; mf < 4; mf++)
#pragma unroll
                for (int nf = 0; nf < 2; nf++) {
                    mma16(aU[mf][nf], av[mf], b1v[nf]);
                    mma16(aG[mf][nf], av[mf], b3v[nf]);
                }
        }
        if (more) {
            STROW(As[buf ^ 1], lr, lh, pa);
            uint32_t* Bdst = isB1 ? B1s[buf ^ 1] : B3s[buf ^ 1];
            STROW(Bdst, br, bh, pb);
        }
        __syncthreads();
        buf ^= 1;
    }
#pragma unroll
    for (int mf = 0; mf < 4; mf++)
#pragma unroll
        for (int half = 0; half < 2; half++) {
            int r = m0 + wm * 64 + mf * 16 + g + half * 8;
            if (r >= cnt) continue;
            float* dst = g_act + (size_t)(off + r) * Fn;
#pragma unroll
            for (int nf = 0; nf < 2; nf++) {
                int c = n0 + wn * 16 + nf * 8 + 2 * t;
                float u0 = aU[mf][nf][half * 2], g0 = aG[mf][nf][half * 2];
                float u1 = aU[mf][nf][half * 2 + 1], g1 = aG[mf][nf][half * 2 + 1];
                *(float2*)(dst + c) = make_float2(u0 / (1.f + expf(-u0)) * g0,
                                                  u1 / (1.f + expf(-u1)) * g1);
            }
        }
}

// ============================================================================
// fp16 MoE GEMM2: ffn = act @ w2^T. CTA 128x128x32 (A rows clamped).
// ============================================================================
__global__ __launch_bounds__(256) void k_h_moe2(const float* __restrict__ w2) {
    int e = blockIdx.z;
    int cnt = g_cnt[e];
    int m0 = blockIdx.y * 128;
    if (m0 >= cnt) return;
    int off = g_off[e];
    int n0 = blockIdx.x * 128;
    const float* A = g_act + (size_t)off * Fn;
    const float* B = w2 + (size_t)e * Dn * Fn;
    __shared__ uint32_t As[2][128 * 20];
    __shared__ uint32_t Bs[2][128 * 20];
    int tid = threadIdx.x, lane = tid & 31, w = tid >> 5;
    int wm = w >> 2, wn = w & 3;
    int g = lane >> 2, t = lane & 3;
    int lr = tid >> 1, lh = tid & 1;
    float acc[4][4][4] = {};
    uint2 pa[4], pb[4];

    int arow = min(m0 + lr, cnt - 1);
    const float* Ab = A + (size_t)arow * Fn + lh * 16;
    const float* Bb = B + (size_t)(n0 + lr) * Fn + lh * 16;
    LOADROW(pa, Ab); LOADROW(pb, Bb);
    STROW(As[0], lr, lh, pa); STROW(Bs[0], lr, lh, pb);
    __syncthreads();

    int nit = Fn >> 5, buf = 0;
    for (int it = 0; it < nit; it++) {
        bool more = (it + 1) < nit;
        if (more) {
            LOADROW(pa, Ab + (it + 1) * 32);
            LOADROW(pb, Bb + (it + 1) * 32);
        }
#pragma unroll
        for (int kk = 0; kk < 2; kk++) {
            uint32_t av[4][4], bv[4][2];
#pragma unroll
            for (int mf = 0; mf < 4; mf++) {
                const uint32_t* p = &As[buf][(wm * 64 + mf * 16 + g) * 20 + kk * 8 + t];
                av[mf][0] = p[0]; av[mf][1] = p[160]; av[mf][2] = p[4]; av[mf][3] = p[164];
            }
#pragma unroll
            for (int nf = 0; nf < 4; nf++) {
                const uint32_t* p = &Bs[buf][(wn * 32 + nf * 8 + g) * 20 + kk * 8 + t];
                bv[nf][0] = p[0]; bv[nf][1] = p[4];
            }
#pragma unroll
            for (int mf = 0; mf < 4; mf++)
#pragma unroll
                for (int nf = 0; nf < 4; nf++) mma16(acc[mf][nf], av[mf], bv[nf]);
        }
        if (more) {
            STROW(As[buf ^ 1], lr, lh, pa);
            STROW(Bs[buf ^ 1], lr, lh, pb);
        }
        __syncthreads();
        buf ^= 1;
    }
#pragma unroll
    for (int mf = 0; mf < 4; mf++) {
        int r1 = m0 + wm * 64 + mf * 16 + g, r2 = r1 + 8;
#pragma unroll
        for (int nf = 0; nf < 4; nf++) {
            int c = n0 + wn * 32 + nf * 8 + 2 * t;
            if (r1 < cnt)
                *(float2*)(g_ffn + (size_t)(off + r1) * Dn + c) = make_float2(acc[mf][nf][0], acc[mf][nf][1]);
            if (r2 < cnt)
                *(float2*)(g_ffn + (size_t)(off + r2) * Dn + c) = make_float2(acc[mf][nf][2], acc[mf][nf][3]);
        }
    }
}

// ---------------- RoPE ----------------
__global__ void k_rope(float* __restrict__ q, float* __restrict__ k) {
    int gid = blockIdx.x * 256 + threadIdx.x;
    if (gid >= Tn * Hn * 64) return;
    int i = gid & 63;
    int h = (gid >> 6) & (Hn - 1);
    int t = gid >> 10;
    int s = t & (Sn - 1);
    float inv = powf(10000.0f, -(float)i / 64.0f);
    float ang = (float)s * inv, sn, c;
    sincosf(ang, &sn, &c);
    size_t base = (size_t)t * Dn + h * HDn;
    float q1 = q[base + i], q2 = q[base + i + 64];
    q[base + i]      = q1 * c - q2 * sn;
    q[base + i + 64] = q2 * c + q1 * sn;
    float k1 = k[base + i], k2 = k[base + i + 64];
    k[base + i]      = k1 * c - k2 * sn;
    k[base + i + 64] = k2 * c + k1 * sn;
}

// ============ tf32 mma.sync flash attention (R4, working) ============
#define ATT_WORDS (128*132 + 64*132 + 64*136 + 128*68)
__global__ __launch_bounds__(256) void k_attn_mma(const float* __restrict__ q,
                                                  const float* __restrict__ k,
                                                  const float* __restrict__ v,
                                                  float* __restrict__ ctx) {
    extern __shared__ uint32_t sm[];
    uint32_t* Qs = sm;
    uint32_t* Ks = Qs + 128 * 132;
    uint32_t* Vs = Ks + 64 * 132;
    uint32_t* Ps = Vs + 64 * 136;
    int tid = threadIdx.x, lane = tid & 31, w = tid >> 5;
    int qt = blockIdx.x, bh = blockIdx.y, b = bh >> 4, h = bh & 15;
    int g = lane >> 2, tig = lane & 3;
    const float scale = 0.08838834764831845f;

    for (int i = 0; i < 16; i++) {
        int idx = tid + 256 * i;
        int r = idx >> 5, c4 = idx & 31;
        float4 val = *(const float4*)(q + (size_t)(b * Sn + qt * 128 + r) * Dn + h * HDn + c4 * 4);
        *(uint4*)(Qs + r * 132 + c4 * 4) =
            make_uint4(f2tf(val.x), f2tf(val.y), f2tf(val.z), f2tf(val.w));
    }
    float o_acc[16][4] = {};
    float mrow0 = -1e30f, mrow1 = -1e30f, lrow0 = 0.f, lrow1 = 0.f;
    int wbase = qt * 128 + w * 16;
    int row_hi = wbase + 15;
    int r0g = wbase + g, r1g = r0g + 8;

    int nkt = 2 * qt + 2;
    for (int kt = 0; kt < nkt; kt++) {
        __syncthreads();
        for (int i = 0; i < 8; i++) {
            int idx = tid + 256 * i;
            int r = idx >> 5, c4 = idx & 31;
            size_t gofs = (size_t)(b * Sn + kt * 64 + r) * Dn + h * HDn + c4 * 4;
            float4 kv = *(const float4*)(k + gofs);
            float4 vv = *(const float4*)(v + gofs);
            *(uint4*)(Ks + r * 132 + c4 * 4) =
                make_uint4(f2tf(kv.x), f2tf(kv.y), f2tf(kv.z), f2tf(kv.w));
            *(uint4*)(Vs + r * 136 + c4 * 4) =
                make_uint4(f2tf(vv.x), f2tf(vv.y), f2tf(vv.z), f2tf(vv.w));
        }
        __syncthreads();
        if (kt * 64 > row_hi) continue;

        float sacc[8][4] = {};
#pragma unroll
        for (int kk = 0; kk < 16; kk++) {
            uint32_t av[4];
            const uint32_t* qp = Qs + (w * 16 + g) * 132 + kk * 8 + tig;
            av[0] = qp[0]; av[1] = qp[8 * 132]; av[2] = qp[4]; av[3] = qp[8 * 132 + 4];
#pragma unroll
            for (int nf = 0; nf < 8; nf++) {
                uint32_t bv[2];
                const uint32_t* kp = Ks + (nf * 8 + g) * 132 + kk * 8 + tig;
                bv[0] = kp[0]; bv[1] = kp[4];
                mma8(sacc[nf], av, bv);
            }
        }
        bool need_mask = (kt * 64 + 63) > wbase;
        float mx0 = -1e30f, mx1 = -1e30f;
#pragma unroll
        for (int nf = 0; nf < 8; nf++) {
            int c0 = kt * 64 + nf * 8 + 2 * tig;
#pragma unroll
            for (int j = 0; j < 4; j++) {
                float s = sacc[nf][j] * scale;
                if (need_mask) {
                    int col = c0 + (j & 1);
                    int rg = (j < 2) ? r0g : r1g;
                    if (col > rg) s = -1e30f;
                }
                sacc[nf][j] = s;
                if (j < 2) mx0 = fmaxf(mx0, s); else mx1 = fmaxf(mx1, s);
            }
        }
        mx0 = fmaxf(mx0, __shfl_xor_sync(0xffffffffu, mx0, 1));
        mx0 = fmaxf(mx0, __shfl_xor_sync(0xffffffffu, mx0, 2));
        mx1 = fmaxf(mx1, __shfl_xor_sync(0xffffffffu, mx1, 1));
        mx1 = fmaxf(mx1, __shfl_xor_sync(0xffffffffu, mx1, 2));
        float mn0 = fmaxf(mrow0, mx0), mn1 = fmaxf(mrow1, mx1);
        float a0 = expf(mrow0 - mn0), a1 = expf(mrow1 - mn1);
        mrow0 = mn0; mrow1 = mn1;
        float sum0 = 0.f, sum1 = 0.f;
#pragma unroll
        for (int nf = 0; nf < 8; nf++) {
            float p0 = expf(sacc[nf][0] - mn0), p1 = expf(sacc[nf][1] - mn0);
            float p2 = expf(sacc[nf][2] - mn1), p3 = expf(sacc[nf][3] - mn1);
            sacc[nf][0] = p0; sacc[nf][1] = p1; sacc[nf][2] = p2; sacc[nf][3] = p3;
            sum0 += p0 + p1; sum1 += p2 + p3;
        }
        sum0 += __shfl_xor_sync(0xffffffffu, sum0, 1);
        sum0 += __shfl_xor_sync(0xffffffffu, sum0, 2);
        sum1 += __shfl_xor_sync(0xffffffffu, sum1, 1);
        sum1 += __shfl_xor_sync(0xffffffffu, sum1, 2);
        lrow0 = lrow0 * a0 + sum0;
        lrow1 = lrow1 * a1 + sum1;
#pragma unroll
        for (int nf = 0; nf < 16; nf++) {
            o_acc[nf][0] *= a0; o_acc[nf][1] *= a0;
            o_acc[nf][2] *= a1; o_acc[nf][3] *= a1;
        }
        int pr0 = w * 16 + g;
#pragma unroll
        for (int nf = 0; nf < 8; nf++) {
            int cb = nf * 8 + 2 * tig;
            Ps[pr0 * 68 + cb]           = f2tf(sacc[nf][0]);
            Ps[pr0 * 68 + cb + 1]       = f2tf(sacc[nf][1]);
            Ps[(pr0 + 8) * 68 + cb]     = f2tf(sacc[nf][2]);
            Ps[(pr0 + 8) * 68 + cb + 1] = f2tf(sacc[nf][3]);
        }
        __syncwarp();
#pragma unroll
        for (int kk = 0; kk < 8; kk++) {
            uint32_t av[4];
            const uint32_t* pp = Ps + (w * 16 + g) * 68 + kk * 8 + tig;
            av[0] = pp[0]; av[1] = pp[8 * 68]; av[2] = pp[4]; av[3] = pp[8 * 68 + 4];
#pragma unroll
            for (int nf = 0; nf < 16; nf++) {
                uint32_t bv[2];
                const uint32_t* vp = Vs + (kk * 8 + tig) * 136 + nf * 8 + g;
                bv[0] = vp[0]; bv[1] = vp[4 * 136];
                mma8(o_acc[nf], av, bv);
            }
        }
        __syncwarp();
    }
    float inv0 = 1.f / lrow0, inv1 = 1.f / lrow1;
    size_t ro0 = (size_t)(b * Sn + r0g) * Dn, ro1 = (size_t)(b * Sn + r1g) * Dn;
#pragma unroll
    for (int nf = 0; nf < 16; nf++) {
        int c = h * HDn + nf * 8 + 2 * tig;
        *(float2*)(ctx + ro0 + c) = make_float2(o_acc[nf][0] * inv0, o_acc[nf][1] * inv0);
        *(float2*)(ctx + ro1 + c) = make_float2(o_acc[nf][2] * inv1, o_acc[nf][3] * inv1);
    }
}

// ---------------- MoE routing ----------------
__global__ void k_zero() { if (threadIdx.x < En) g_cnt[threadIdx.x] = 0; }

__global__ void k_route(const float* __restrict__ h2, const float* __restrict__ gw) {
    int t = blockIdx.x;
    int lane = threadIdx.x & 31, wid = threadIdx.x >> 5;
    const float* hr = h2 + (size_t)t * Dn;
    const float* gr = gw + (size_t)wid * Dn;
    float s = 0.f;
    for (int i = lane; i < Dn; i += 32) s += hr[i] * gr[i];
    for (int o = 16; o; o >>= 1) s += __shfl_down_sync(0xffffffffu, s, o);
    __shared__ float lg[En];
    if (lane == 0) lg[wid] = s;
    __syncthreads();
    if (threadIdx.x == 0) {
        float mx = lg[0];
        for (int e = 1; e < En; e++) mx = fmaxf(mx, lg[e]);
        float p[En];
        for (int e = 0; e < En; e++) p[e] = expf(lg[e] - mx);
        int i1 = 0;
        for (int e = 1; e < En; e++) if (p[e] > p[i1]) i1 = e;
        int i2 = (i1 == 0) ? 1 : 0;
        for (int e = 0; e < En; e++) { if (e == i1) continue; if (p[e] > p[i2]) i2 = e; }
        float norm = p[i1] + p[i2];
        g_tok_e[t * 2]     = i1; g_tok_w[t * 2]     = p[i1] / norm;
        g_tok_e[t * 2 + 1] = i2; g_tok_w[t * 2 + 1] = p[i2] / norm;
        atomicAdd(&g_cnt[i1], 1);
        atomicAdd(&g_cnt[i2], 1);
    }
}

__global__ void k_scan() {
    if (threadIdx.x == 0) {
        int o = 0;
        for (int e = 0; e < En; e++) { g_off[e] = o; o += g_cnt[e]; g_run[e] = 0; }
    }
}

__global__ void k_place() {
    int t = blockIdx.x * 256 + threadIdx.x;
    if (t >= Tn) return;
    for (int kk = 0; kk < KKn; kk++) {
        int e = g_tok_e[t * 2 + kk];
        int pos = g_off[e] + atomicAdd(&g_run[e], 1);
        g_list_tok[pos] = t;
        g_tok_pos[t * 2 + kk] = pos;
    }
}

// ---------------- final combine ----------------
__global__ void k_final(float* __restrict__ out) {
    int t = blockIdx.x;
    int p0 = g_tok_pos[t * 2], p1 = g_tok_pos[t * 2 + 1];
    float w0 = g_tok_w[t * 2], w1 = g_tok_w[t * 2 + 1];
    const float4* x1 = (const float4*)(g_x1 + (size_t)t * Dn);
    const float4* f0 = (const float4*)(g_ffn + (size_t)p0 * Dn);
    const float4* f1 = (const float4*)(g_ffn + (size_t)p1 * Dn);
    float4* o = (float4*)(out + (size_t)t * Dn);
    for (int c = threadIdx.x; c < Dn / 4; c += 256) {
        float4 a = x1[c], b = f0[c], d = f1[c];
        a.x += w0 * b.x + w1 * d.x;
        a.y += w0 * b.y + w1 * d.y;
        a.z += w0 * b.z + w1 * d.z;
        a.w += w0 * b.w + w1 * d.w;
        o[c] = a;
    }
}

extern "C" void kernel_launch(void* const* d_in, const int* in_sizes, int n_in,
                              void* d_out, int out_size) {
    (void)in_sizes; (void)n_in; (void)out_size;
    const float* x   = (const float*)d_in[0];
    const float* ln1 = (const float*)d_in[3];
    const float* wq  = (const float*)d_in[4];
    const float* wk  = (const float*)d_in[5];
    const float* wv  = (const float*)d_in[6];
    const float* wo  = (const float*)d_in[7];
    const float* ln2 = (const float*)d_in[8];
    const float* gw  = (const float*)d_in[9];
    const float* w1  = (const float*)d_in[10];
    const float* w3  = (const float*)d_in[11];
    const float* w2  = (const float*)d_in[12];
    float* out = (float*)d_out;

    float *h1, *qb, *kb, *vb, *cb, *x1b, *h2b;
    cudaGetSymbolAddress((void**)&h1,  g_h1);
    cudaGetSymbolAddress((void**)&qb,  g_q);
    cudaGetSymbolAddress((void**)&kb,  g_k);
    cudaGetSymbolAddress((void**)&vb,  g_v);
    cudaGetSymbolAddress((void**)&cb,  g_ctx);
    cudaGetSymbolAddress((void**)&x1b, g_x1);
    cudaGetSymbolAddress((void**)&h2b, g_h2);

    const int smem_attn = ATT_WORDS * 4;
    cudaFuncSetAttribute(k_attn_mma, cudaFuncAttributeMaxDynamicSharedMemorySize, smem_attn);

    k_rmsnorm<<<Tn, 256>>>(x, ln1, h1);
    dim3 g1(Dn / 128, Tn / 128);
    k_h_gemm<<<g1, 256>>>(h1, wq, nullptr, qb, Tn, Dn, Dn);
    k_h_gemm<<<g1, 256>>>(h1, wk, nullptr, kb, Tn, Dn, Dn);
    k_h_gemm<<<g1, 256>>>(h1, wv, nullptr, vb, Tn, Dn, Dn);
    k_rope<<<(Tn * Hn * 64) / 256, 256>>>(qb, kb);
    dim3 ga(Sn / 128, Bn * Hn);
    k_attn_mma<<<ga, 256, smem_attn>>>(qb, kb, vb, cb);
    k_h_gemm<<<g1, 256>>>(cb, wo, x, x1b, Tn, Dn, Dn);
    k_rmsnorm<<<Tn, 256>>>(x1b, ln2, h2b);
    k_zero<<<1, 32>>>();
    k_route<<<Tn, 256>>>(h2b, gw);
    k_scan<<<1, 32>>>();
    k_place<<<Tn / 256, 256>>>();
    dim3 gm1(Fn / 64, Tn / 128, En);
    k_h_moe1<<<gm1, 256>>>(h2b, w1, w3);
    dim3 gm2(Dn / 128, Tn / 128, En);
    k_h_moe2<<<gm2, 256>>>(w2);
    k_final<<<Tn, 256>>>(out);
}